// round 1
// baseline (speedup 1.0000x reference)
#include <cuda_runtime.h>
#include <math.h>

#define BB 2
#define SS 2048
#define SA 2051            // S + 3 physics tokens
#define HID 1024
#define NH 16
#define HD 64
#define MTOT (BB*SA)       // 4102
#define APAD 68            // padded row stride (floats) for attention smem tiles

// ---------------- device scratch (no allocations allowed) ----------------
__device__ float g_augC[BB*SA*HID];
__device__ float g_augL[BB*SA*HID];
__device__ float g_Qc[BB*SA*HID];
__device__ float g_Kc[BB*SA*HID];
__device__ float g_Vc[BB*SA*HID];
__device__ float g_Ql[BB*SA*HID];
__device__ float g_Kl[BB*SA*HID];
__device__ float g_Vl[BB*SA*HID];
__device__ float g_attC[BB*SA*HID];
__device__ float g_attL[BB*SA*HID];

// ---------------- build augmented sequences ----------------
__global__ void build_aug_kernel(const float* __restrict__ cnn,
                                 const float* __restrict__ llm,
                                 const float* __restrict__ energy,
                                 const float* __restrict__ mass,
                                 const float* __restrict__ momentum) {
    int idx = blockIdx.x * blockDim.x + threadIdx.x;   // float4 index
    const int total = BB * SA * HID / 4;
    if (idx >= total) return;
    int h4  = idx % (HID / 4);
    int row = idx / (HID / 4);
    int s   = row % SA;
    int b   = row / SA;
    float4 vC, vL;
    if (s < SS) {
        vC = ((const float4*)cnn)[(size_t)(b * SS + s) * (HID / 4) + h4];
        vL = ((const float4*)llm)[(size_t)(b * SS + s) * (HID / 4) + h4];
    } else {
        const float* e = (s == SS) ? energy : ((s == SS + 1) ? mass : momentum);
        vC = ((const float4*)e)[h4];
        vL = vC;
    }
    ((float4*)g_augC)[idx] = vC;
    ((float4*)g_augL)[idx] = vL;
}

// ---------------- fp32 GEMM: C[M,1024] = A[M,1024] @ W[1024,1024] + bias ----------------
__global__ __launch_bounds__(256) void gemm_bias_kernel(
    const float* __restrict__ A, const float* __restrict__ W,
    const float* __restrict__ bias, float* __restrict__ C, int M) {
    __shared__ float As[8][128];   // transposed A tile: As[k][m]
    __shared__ float Bs[8][128];   // Bs[k][n]
    const int tid  = threadIdx.x;
    const int row0 = blockIdx.y * 128;
    const int col0 = blockIdx.x * 128;
    const int tx = tid & 15;
    const int ty = tid >> 4;
    const int a_row = tid >> 1;
    const int a_col = (tid & 1) * 4;
    const int b_row = tid >> 5;
    const int b_col = (tid & 31) * 4;

    float acc[8][8];
#pragma unroll
    for (int i = 0; i < 8; i++)
#pragma unroll
        for (int j = 0; j < 8; j++) acc[i][j] = 0.f;

    const bool a_ok = (row0 + a_row) < M;
    const float* Aptr = A + (size_t)(row0 + a_row) * HID + a_col;
    const float* Wptr = W + (size_t)b_row * HID + col0 + b_col;

    for (int k0 = 0; k0 < HID; k0 += 8) {
        float4 av = make_float4(0.f, 0.f, 0.f, 0.f);
        if (a_ok) av = *(const float4*)(Aptr + k0);
        As[a_col + 0][a_row] = av.x;
        As[a_col + 1][a_row] = av.y;
        As[a_col + 2][a_row] = av.z;
        As[a_col + 3][a_row] = av.w;
        float4 bv = *(const float4*)(Wptr + (size_t)k0 * HID);
        *(float4*)&Bs[b_row][b_col] = bv;
        __syncthreads();
#pragma unroll
        for (int kk = 0; kk < 8; kk++) {
            float a[8], b[8];
            *(float4*)(a)     = *(const float4*)&As[kk][ty * 8];
            *(float4*)(a + 4) = *(const float4*)&As[kk][ty * 8 + 4];
            *(float4*)(b)     = *(const float4*)&Bs[kk][tx * 8];
            *(float4*)(b + 4) = *(const float4*)&Bs[kk][tx * 8 + 4];
#pragma unroll
            for (int i = 0; i < 8; i++)
#pragma unroll
                for (int j = 0; j < 8; j++) acc[i][j] += a[i] * b[j];
        }
        __syncthreads();
    }

#pragma unroll
    for (int i = 0; i < 8; i++) {
        int gr = row0 + ty * 8 + i;
        if (gr < M) {
            float* Cp = C + (size_t)gr * HID + col0 + tx * 8;
#pragma unroll
            for (int j = 0; j < 8; j++) Cp[j] = acc[i][j] + bias[col0 + tx * 8 + j];
        }
    }
}

// ---------------- flash cross-attention (softmax biases are per-row constants -> dropped) ----
// grid: (q_tiles=33, B*NH=32, 2 calls). 256 threads. Tq=Tk=64, D=64.
// Thread map: tx=tid&15 (k or d cols, x4), ty=tid>>4 (q rows, x4).
__global__ __launch_bounds__(256) void attn_kernel(
    const float* __restrict__ Q0, const float* __restrict__ K0,
    const float* __restrict__ V0, float* __restrict__ O0,
    const float* __restrict__ Q1, const float* __restrict__ K1,
    const float* __restrict__ V1, float* __restrict__ O1) {
    extern __shared__ float sm[];
    float* Qs = sm;                  // [64][APAD]
    float* Ks = sm + 64 * APAD;      // reused as P after S is in registers
    float* Vs = sm + 2 * 64 * APAD;

    const int tid = threadIdx.x;
    const int tx = tid & 15;
    const int ty = tid >> 4;
    const int qt = blockIdx.x;
    const int bh = blockIdx.y;
    const int b = bh >> 4, h = bh & 15;

    const float* Q = blockIdx.z ? Q1 : Q0;
    const float* K = blockIdx.z ? K1 : K0;
    const float* V = blockIdx.z ? V1 : V0;
    float*       O = blockIdx.z ? O1 : O0;

    const int q0 = qt * 64;
    const size_t baseBH = (size_t)b * SA * HID + (size_t)h * HD;

    // load Q tile (zero-fill OOB rows)
    for (int t = tid; t < 64 * 16; t += 256) {
        int r = t >> 4, c4 = (t & 15) * 4;
        float4 v = make_float4(0.f, 0.f, 0.f, 0.f);
        if (q0 + r < SA) v = *(const float4*)&Q[baseBH + (size_t)(q0 + r) * HID + c4];
        *(float4*)&Qs[r * APAD + c4] = v;
    }

    float acc[4][4];
#pragma unroll
    for (int i = 0; i < 4; i++)
#pragma unroll
        for (int j = 0; j < 4; j++) acc[i][j] = 0.f;
    float mrow[4], lrow[4];
#pragma unroll
    for (int i = 0; i < 4; i++) { mrow[i] = -INFINITY; lrow[i] = 0.f; }

    __syncthreads();

    for (int k0 = 0; k0 < SA; k0 += 64) {
        // load K,V tiles (zero-fill OOB rows; zeros in V keep 0*V = 0, no NaN)
        for (int t = tid; t < 64 * 16; t += 256) {
            int r = t >> 4, c4 = (t & 15) * 4;
            float4 kv = make_float4(0.f, 0.f, 0.f, 0.f);
            float4 vv = kv;
            if (k0 + r < SA) {
                size_t g = baseBH + (size_t)(k0 + r) * HID + c4;
                kv = *(const float4*)&K[g];
                vv = *(const float4*)&V[g];
            }
            *(float4*)&Ks[r * APAD + c4] = kv;
            *(float4*)&Vs[r * APAD + c4] = vv;
        }
        __syncthreads();

        // S = Q @ K^T (4x4 per thread)
        float s[4][4];
#pragma unroll
        for (int i = 0; i < 4; i++)
#pragma unroll
            for (int j = 0; j < 4; j++) s[i][j] = 0.f;

#pragma unroll 4
        for (int d = 0; d < 64; d += 4) {
            float4 qv[4], kv[4];
#pragma unroll
            for (int i = 0; i < 4; i++) qv[i] = *(const float4*)&Qs[(ty * 4 + i) * APAD + d];
#pragma unroll
            for (int j = 0; j < 4; j++) kv[j] = *(const float4*)&Ks[(tx * 4 + j) * APAD + d];
#pragma unroll
            for (int i = 0; i < 4; i++)
#pragma unroll
                for (int j = 0; j < 4; j++)
                    s[i][j] += qv[i].x * kv[j].x + qv[i].y * kv[j].y +
                               qv[i].z * kv[j].z + qv[i].w * kv[j].w;
        }

        // scale + mask invalid k columns
        const int kleft = SA - k0;
#pragma unroll
        for (int j = 0; j < 4; j++) {
            bool valid = (tx * 4 + j) < kleft;
#pragma unroll
            for (int i = 0; i < 4; i++)
                s[i][j] = valid ? s[i][j] * 0.125f : -1e30f;
        }

        // online softmax: stats replicated across the 16-lane row group
        float corr[4];
#pragma unroll
        for (int i = 0; i < 4; i++) {
            float m = fmaxf(fmaxf(s[i][0], s[i][1]), fmaxf(s[i][2], s[i][3]));
#pragma unroll
            for (int msk = 8; msk >= 1; msk >>= 1)
                m = fmaxf(m, __shfl_xor_sync(0xffffffffu, m, msk));
            float mnew = fmaxf(mrow[i], m);
            corr[i] = __expf(mrow[i] - mnew);
            mrow[i] = mnew;
            float rs = 0.f;
#pragma unroll
            for (int j = 0; j < 4; j++) {
                float p = __expf(s[i][j] - mnew);
                s[i][j] = p;
                rs += p;
            }
#pragma unroll
            for (int msk = 8; msk >= 1; msk >>= 1)
                rs += __shfl_xor_sync(0xffffffffu, rs, msk);
            lrow[i] = lrow[i] * corr[i] + rs;
        }

        __syncthreads();   // everyone done reading Ks
        // write P into the K buffer
#pragma unroll
        for (int i = 0; i < 4; i++)
            *(float4*)&Ks[(ty * 4 + i) * APAD + tx * 4] =
                make_float4(s[i][0], s[i][1], s[i][2], s[i][3]);
        __syncthreads();

        // rescale running accumulator, then O += P @ V
#pragma unroll
        for (int i = 0; i < 4; i++)
#pragma unroll
            for (int j = 0; j < 4; j++) acc[i][j] *= corr[i];

#pragma unroll 4
        for (int k = 0; k < 64; k += 4) {
            float4 p4[4];
#pragma unroll
            for (int i = 0; i < 4; i++) p4[i] = *(const float4*)&Ks[(ty * 4 + i) * APAD + k];
            float4 v0 = *(const float4*)&Vs[(k + 0) * APAD + tx * 4];
            float4 v1 = *(const float4*)&Vs[(k + 1) * APAD + tx * 4];
            float4 v2 = *(const float4*)&Vs[(k + 2) * APAD + tx * 4];
            float4 v3 = *(const float4*)&Vs[(k + 3) * APAD + tx * 4];
#pragma unroll
            for (int i = 0; i < 4; i++) {
                acc[i][0] += p4[i].x * v0.x + p4[i].y * v1.x + p4[i].z * v2.x + p4[i].w * v3.x;
                acc[i][1] += p4[i].x * v0.y + p4[i].y * v1.y + p4[i].z * v2.y + p4[i].w * v3.y;
                acc[i][2] += p4[i].x * v0.z + p4[i].y * v1.z + p4[i].z * v2.z + p4[i].w * v3.z;
                acc[i][3] += p4[i].x * v0.w + p4[i].y * v1.w + p4[i].z * v2.w + p4[i].w * v3.w;
            }
        }
        __syncthreads();   // before next tile overwrites Ks/Vs
    }

    // epilogue: normalize and store
#pragma unroll
    for (int i = 0; i < 4; i++) {
        int qr = q0 + ty * 4 + i;
        if (qr < SA) {
            float inv = 1.0f / lrow[i];
            float4 o = make_float4(acc[i][0] * inv, acc[i][1] * inv,
                                   acc[i][2] * inv, acc[i][3] * inv);
            *(float4*)&O[baseBH + (size_t)qr * HID + tx * 4] = o;
        }
    }
}

// ---------------- residual + LayerNorm + slice -> output ----------------
// one CTA (128 threads) per output row; rows = 2 calls * B * S = 8192
__global__ __launch_bounds__(128) void ln_out_kernel(
    const float* __restrict__ gamma, const float* __restrict__ beta,
    float* __restrict__ out) {
    __shared__ float sbuf[4];
    const int row = blockIdx.x;
    const int c = row >> 12;        // / 4096
    const int r = row & 4095;
    const int b = r >> 11;          // / 2048
    const int s = r & 2047;
    const float* aug  = c ? g_augL : g_augC;
    const float* proj = c ? g_Ql   : g_Qc;   // out-proj results were written here
    const size_t base = ((size_t)b * SA + s) * HID;
    const int tid = threadIdx.x;

    float x[8];
    float4 a0 = *(const float4*)&aug[base + tid * 8];
    float4 a1 = *(const float4*)&aug[base + tid * 8 + 4];
    float4 p0 = *(const float4*)&proj[base + tid * 8];
    float4 p1 = *(const float4*)&proj[base + tid * 8 + 4];
    x[0] = a0.x + p0.x; x[1] = a0.y + p0.y; x[2] = a0.z + p0.z; x[3] = a0.w + p0.w;
    x[4] = a1.x + p1.x; x[5] = a1.y + p1.y; x[6] = a1.z + p1.z; x[7] = a1.w + p1.w;

    float sum = 0.f;
#pragma unroll
    for (int j = 0; j < 8; j++) sum += x[j];
#pragma unroll
    for (int m = 16; m >= 1; m >>= 1) sum += __shfl_xor_sync(0xffffffffu, sum, m);
    if ((tid & 31) == 0) sbuf[tid >> 5] = sum;
    __syncthreads();
    float mu = (sbuf[0] + sbuf[1] + sbuf[2] + sbuf[3]) * (1.0f / HID);
    __syncthreads();

    float vs = 0.f;
#pragma unroll
    for (int j = 0; j < 8; j++) { float d = x[j] - mu; vs += d * d; }
#pragma unroll
    for (int m = 16; m >= 1; m >>= 1) vs += __shfl_xor_sync(0xffffffffu, vs, m);
    if ((tid & 31) == 0) sbuf[tid >> 5] = vs;
    __syncthreads();
    float var = (sbuf[0] + sbuf[1] + sbuf[2] + sbuf[3]) * (1.0f / HID);
    float rstd = rsqrtf(var + 1e-5f);

    float* op = out + (size_t)c * (BB * SS * HID) + ((size_t)b * SS + s) * HID + tid * 8;
    float o[8];
#pragma unroll
    for (int j = 0; j < 8; j++) {
        int col = tid * 8 + j;
        o[j] = (x[j] - mu) * rstd * gamma[col] + beta[col];
    }
    *(float4*)(op)     = make_float4(o[0], o[1], o[2], o[3]);
    *(float4*)(op + 4) = make_float4(o[4], o[5], o[6], o[7]);
}

// ---------------- launch ----------------
extern "C" void kernel_launch(void* const* d_in, const int* in_sizes, int n_in,
                              void* d_out, int out_size) {
    const float* cnn      = (const float*)d_in[0];
    const float* llm      = (const float*)d_in[1];
    const float* Wq       = (const float*)d_in[2];
    const float* bq       = (const float*)d_in[3];
    const float* Wk       = (const float*)d_in[4];
    const float* bk       = (const float*)d_in[5];
    const float* Wv       = (const float*)d_in[6];
    const float* bv       = (const float*)d_in[7];
    const float* Wo       = (const float*)d_in[8];
    const float* bo       = (const float*)d_in[9];
    const float* energy   = (const float*)d_in[10];
    const float* mass     = (const float*)d_in[11];
    const float* momentum = (const float*)d_in[12];
    const float* gamma    = (const float*)d_in[13];
    const float* beta     = (const float*)d_in[14];
    float* out = (float*)d_out;

    float *augC, *augL, *Qc, *Kc, *Vc, *Ql, *Kl, *Vl, *attC, *attL;
    cudaGetSymbolAddress((void**)&augC, g_augC);
    cudaGetSymbolAddress((void**)&augL, g_augL);
    cudaGetSymbolAddress((void**)&Qc,   g_Qc);
    cudaGetSymbolAddress((void**)&Kc,   g_Kc);
    cudaGetSymbolAddress((void**)&Vc,   g_Vc);
    cudaGetSymbolAddress((void**)&Ql,   g_Ql);
    cudaGetSymbolAddress((void**)&Kl,   g_Kl);
    cudaGetSymbolAddress((void**)&Vl,   g_Vl);
    cudaGetSymbolAddress((void**)&attC, g_attC);
    cudaGetSymbolAddress((void**)&attL, g_attL);

    const int tot4 = BB * SA * HID / 4;
    build_aug_kernel<<<(tot4 + 255) / 256, 256>>>(cnn, llm, energy, mass, momentum);

    dim3 ggrid(HID / 128, (MTOT + 127) / 128);
    gemm_bias_kernel<<<ggrid, 256>>>(augC, Wq, bq, Qc, MTOT);
    gemm_bias_kernel<<<ggrid, 256>>>(augC, Wk, bk, Kc, MTOT);
    gemm_bias_kernel<<<ggrid, 256>>>(augC, Wv, bv, Vc, MTOT);
    gemm_bias_kernel<<<ggrid, 256>>>(augL, Wq, bq, Ql, MTOT);
    gemm_bias_kernel<<<ggrid, 256>>>(augL, Wk, bk, Kl, MTOT);
    gemm_bias_kernel<<<ggrid, 256>>>(augL, Wv, bv, Vl, MTOT);

    const int smem = 3 * 64 * APAD * 4;   // 52224 B
    cudaFuncSetAttribute(attn_kernel, cudaFuncAttributeMaxDynamicSharedMemorySize, smem);
    dim3 agrid((SA + 63) / 64, BB * NH, 2);
    attn_kernel<<<agrid, 256, smem>>>(Qc, Kl, Vl, attC, Ql, Kc, Vc, attL);

    // output projections (reuse Q buffers as proj buffers)
    gemm_bias_kernel<<<ggrid, 256>>>(attC, Wo, bo, Qc, MTOT);
    gemm_bias_kernel<<<ggrid, 256>>>(attL, Wo, bo, Ql, MTOT);

    ln_out_kernel<<<2 * BB * SS, 128>>>(gamma, beta, out);
}

// round 3
// speedup vs baseline: 1.2031x; 1.2031x over previous
#include <cuda_runtime.h>
#include <cuda_bf16.h>
#include <math.h>
#include <cstdint>

#define BB 2
#define SS 2048
#define SA 2051            // S + 3 physics tokens
#define HID 1024
#define NH 16
#define HD 64
#define STREAM (BB*SA*HID) // floats per stream
#define MTOT2 (2*BB*SA)    // 8204 merged rows
#define APAD 68            // padded row stride (floats) for attention smem tiles

// ---------------- GEMM (mma.sync bf16, split) tiling ----------------
#define TM 128
#define TN 128
#define KC 32
#define NCHUNK (HID/KC)    // 32
#define A_STR 80           // smem bytes per A row (64 data + 16 pad)
#define B_STR 272          // smem bytes per B row (256 data + 16 pad)
#define SM_AHI 0
#define SM_ALO (128*A_STR)            // 10240
#define SM_BHI (2*128*A_STR)          // 20480
#define SM_BLO (SM_BHI + 32*B_STR)    // 29184
#define GEMM_SMEM (SM_BLO + 32*B_STR) // 37888

// ---------------- device scratch (no allocations allowed) ----------------
__device__ float g_aug[2*STREAM];
__device__ float g_Q[2*STREAM];
__device__ float g_K[2*STREAM];
__device__ float g_V[2*STREAM];
__device__ float g_att[2*STREAM];

// ---------------- helpers ----------------
__device__ __forceinline__ uint32_t smem_u32(const void* p) {
    uint32_t a;
    asm("{ .reg .u64 t; cvta.to.shared.u64 t, %1; cvt.u32.u64 %0, t; }" : "=r"(a) : "l"(p));
    return a;
}
__device__ __forceinline__ void mma16816(float* d, const uint32_t* a, const uint32_t* b) {
    asm volatile(
        "mma.sync.aligned.m16n8k16.row.col.f32.bf16.bf16.f32 "
        "{%0,%1,%2,%3}, {%4,%5,%6,%7}, {%8,%9}, {%0,%1,%2,%3};"
        : "+f"(d[0]), "+f"(d[1]), "+f"(d[2]), "+f"(d[3])
        : "r"(a[0]), "r"(a[1]), "r"(a[2]), "r"(a[3]), "r"(b[0]), "r"(b[1]));
}
__device__ __forceinline__ void ldmx4(uint32_t* r, uint32_t addr) {
    asm volatile("ldmatrix.sync.aligned.m8n8.x4.shared.b16 {%0,%1,%2,%3}, [%4];"
                 : "=r"(r[0]), "=r"(r[1]), "=r"(r[2]), "=r"(r[3]) : "r"(addr));
}
__device__ __forceinline__ void ldmx4t(uint32_t* r, uint32_t addr) {
    asm volatile("ldmatrix.sync.aligned.m8n8.x4.trans.shared.b16 {%0,%1,%2,%3}, [%4];"
                 : "=r"(r[0]), "=r"(r[1]), "=r"(r[2]), "=r"(r[3]) : "r"(addr));
}
__device__ __forceinline__ uint32_t pk_bf2(__nv_bfloat16 a, __nv_bfloat16 b) {
    __nv_bfloat162 t(a, b);
    return *reinterpret_cast<uint32_t*>(&t);
}
__device__ __forceinline__ void split2(float f, __nv_bfloat16& h, __nv_bfloat16& l) {
    h = __float2bfloat16(f);
    l = __float2bfloat16(f - __bfloat162float(h));
}

// ---------------- build augmented sequences ----------------
__global__ void build_aug_kernel(const float* __restrict__ cnn,
                                 const float* __restrict__ llm,
                                 const float* __restrict__ energy,
                                 const float* __restrict__ mass,
                                 const float* __restrict__ momentum) {
    int idx = blockIdx.x * blockDim.x + threadIdx.x;   // float4 index
    const int total = BB * SA * HID / 4;
    if (idx >= total) return;
    int h4  = idx % (HID / 4);
    int row = idx / (HID / 4);
    int s   = row % SA;
    int b   = row / SA;
    float4 vC, vL;
    if (s < SS) {
        vC = ((const float4*)cnn)[(size_t)(b * SS + s) * (HID / 4) + h4];
        vL = ((const float4*)llm)[(size_t)(b * SS + s) * (HID / 4) + h4];
    } else {
        const float* e = (s == SS) ? energy : ((s == SS + 1) ? mass : momentum);
        vC = ((const float4*)e)[h4];
        vL = vC;
    }
    ((float4*)g_aug)[idx] = vC;
    ((float4*)g_aug)[idx + STREAM / 4] = vL;
}

// ---------------- tensor-core GEMM: C[M,1024] = A[M,1024] @ W + bias ----------------
// bf16 2-term split (Ah*Bh + Ah*Bl + Al*Bh), fp32 accum. grid (8, ceil(M/128)), 256 thr.
__global__ __launch_bounds__(256, 1) void gemm_mma_kernel(
    const float* __restrict__ A, const float* __restrict__ W,
    const float* __restrict__ bias, float* __restrict__ C, int M) {
    extern __shared__ char smc[];
    const uint32_t sb = smem_u32(smc);
    const int tid = threadIdx.x, lane = tid & 31, wid = tid >> 5;
    const int wm = wid >> 2, wn = wid & 3;           // warp grid 2(m) x 4(n)
    const int row0 = blockIdx.y * TM, col0 = blockIdx.x * TN;

    // global load mapping
    const int arow = tid >> 1, acol = (tid & 1) * 16;  // A: 128 rows x 32 cols
    const int bk = tid >> 3, bn = (tid & 7) * 16;      // B: 32 k-rows x 128 n
    const bool a_ok = (row0 + arow) < M;
    const float* Ag = A + (size_t)(row0 + arow) * HID + acol;
    const float* Wg = W + (size_t)bk * HID + col0 + bn;

    float pa[16], pb[16];
#pragma unroll
    for (int i = 0; i < 4; i++) {
        float4 v = a_ok ? *(const float4*)(Ag + i * 4) : make_float4(0.f, 0.f, 0.f, 0.f);
        pa[4*i] = v.x; pa[4*i+1] = v.y; pa[4*i+2] = v.z; pa[4*i+3] = v.w;
        float4 w = *(const float4*)(Wg + i * 4);
        pb[4*i] = w.x; pb[4*i+1] = w.y; pb[4*i+2] = w.z; pb[4*i+3] = w.w;
    }

    float acc[4][4][4];
#pragma unroll
    for (int i = 0; i < 4; i++)
#pragma unroll
        for (int j = 0; j < 4; j++)
#pragma unroll
            for (int k = 0; k < 4; k++) acc[i][j][k] = 0.f;

    // per-lane ldmatrix offsets
    const uint32_t a_lane = (uint32_t)((lane & 15) * A_STR + (lane >> 4) * 16);
    const uint32_t b_lane = (uint32_t)(((((lane >> 3) & 1) * 8) + (lane & 7)) * B_STR
                                       + (lane >> 4) * 16);

    for (int ch = 0; ch < NCHUNK; ch++) {
        // convert + store prefetched chunk to smem
        {
            uint32_t h[8], l[8];
#pragma unroll
            for (int j = 0; j < 8; j++) {
                __nv_bfloat16 h0, l0, h1, l1;
                split2(pa[2*j], h0, l0); split2(pa[2*j+1], h1, l1);
                h[j] = pk_bf2(h0, h1); l[j] = pk_bf2(l0, l1);
            }
            char* ab = smc + arow * A_STR + acol * 2;
            *(uint4*)(ab + SM_AHI)      = make_uint4(h[0], h[1], h[2], h[3]);
            *(uint4*)(ab + SM_AHI + 16) = make_uint4(h[4], h[5], h[6], h[7]);
            *(uint4*)(ab + SM_ALO)      = make_uint4(l[0], l[1], l[2], l[3]);
            *(uint4*)(ab + SM_ALO + 16) = make_uint4(l[4], l[5], l[6], l[7]);
#pragma unroll
            for (int j = 0; j < 8; j++) {
                __nv_bfloat16 h0, l0, h1, l1;
                split2(pb[2*j], h0, l0); split2(pb[2*j+1], h1, l1);
                h[j] = pk_bf2(h0, h1); l[j] = pk_bf2(l0, l1);
            }
            char* bb = smc + bk * B_STR + bn * 2;
            *(uint4*)(bb + SM_BHI)      = make_uint4(h[0], h[1], h[2], h[3]);
            *(uint4*)(bb + SM_BHI + 16) = make_uint4(h[4], h[5], h[6], h[7]);
            *(uint4*)(bb + SM_BLO)      = make_uint4(l[0], l[1], l[2], l[3]);
            *(uint4*)(bb + SM_BLO + 16) = make_uint4(l[4], l[5], l[6], l[7]);
        }
        __syncthreads();

        // prefetch next chunk (global) — latency hidden under the MMA block below
        if (ch + 1 < NCHUNK) {
            const float* ap = Ag + (ch + 1) * KC;
            const float* wp = Wg + (size_t)(ch + 1) * KC * HID;
#pragma unroll
            for (int i = 0; i < 4; i++) {
                float4 v = a_ok ? *(const float4*)(ap + i * 4) : make_float4(0.f, 0.f, 0.f, 0.f);
                pa[4*i] = v.x; pa[4*i+1] = v.y; pa[4*i+2] = v.z; pa[4*i+3] = v.w;
                float4 w = *(const float4*)(wp + i * 4);
                pb[4*i] = w.x; pb[4*i+1] = w.y; pb[4*i+2] = w.z; pb[4*i+3] = w.w;
            }
        }

        // compute: 2 k16-steps x (4m x 4n) x 3 split terms
#pragma unroll
        for (int ks = 0; ks < 2; ks++) {
            uint32_t ahi[4][4], alo[4][4], bhi[4][2], blo[4][2];
#pragma unroll
            for (int mt = 0; mt < 4; mt++) {
                uint32_t ao = sb + (uint32_t)((wm * 64 + mt * 16) * A_STR + ks * 32) + a_lane;
                ldmx4(ahi[mt], ao + SM_AHI);
                ldmx4(alo[mt], ao + SM_ALO);
            }
            {
                uint32_t bo = sb + (uint32_t)(ks * 16 * B_STR + wn * 64) + b_lane;
                uint32_t t[4];
                ldmx4t(t, bo + SM_BHI);
                bhi[0][0]=t[0]; bhi[0][1]=t[1]; bhi[1][0]=t[2]; bhi[1][1]=t[3];
                ldmx4t(t, bo + SM_BHI + 32);
                bhi[2][0]=t[0]; bhi[2][1]=t[1]; bhi[3][0]=t[2]; bhi[3][1]=t[3];
                ldmx4t(t, bo + SM_BLO);
                blo[0][0]=t[0]; blo[0][1]=t[1]; blo[1][0]=t[2]; blo[1][1]=t[3];
                ldmx4t(t, bo + SM_BLO + 32);
                blo[2][0]=t[0]; blo[2][1]=t[1]; blo[3][0]=t[2]; blo[3][1]=t[3];
            }
#pragma unroll
            for (int mt = 0; mt < 4; mt++)
#pragma unroll
                for (int nt = 0; nt < 4; nt++) {
                    mma16816(acc[mt][nt], ahi[mt], bhi[nt]);
                    mma16816(acc[mt][nt], ahi[mt], blo[nt]);
                    mma16816(acc[mt][nt], alo[mt], bhi[nt]);
                }
        }
        __syncthreads();
    }

    // epilogue: d-frag rows l>>2 (+8), cols (l&3)*2 (+1)
    const int mb = row0 + wm * 64 + (lane >> 2);
    const int nb = col0 + wn * 32 + (lane & 3) * 2;
#pragma unroll
    for (int nt = 0; nt < 4; nt++) {
        const int n = nb + nt * 8;
        const float2 bv = *(const float2*)&bias[n];
#pragma unroll
        for (int mt = 0; mt < 4; mt++) {
            const int m = mb + mt * 16;
            if (m < M)
                *(float2*)&C[(size_t)m * HID + n] =
                    make_float2(acc[mt][nt][0] + bv.x, acc[mt][nt][1] + bv.y);
            if (m + 8 < M)
                *(float2*)&C[(size_t)(m + 8) * HID + n] =
                    make_float2(acc[mt][nt][2] + bv.x, acc[mt][nt][3] + bv.y);
        }
    }
}

// ---------------- flash cross-attention (per-row softmax biases drop out exactly) ----
// grid: (33, B*NH=32, 2 streams). 256 threads.
__global__ __launch_bounds__(256) void attn_kernel() {
    extern __shared__ float sm[];
    float* Qs = sm;
    float* Ks = sm + 64 * APAD;
    float* Vs = sm + 2 * 64 * APAD;

    const int tid = threadIdx.x;
    const int tx = tid & 15;
    const int ty = tid >> 4;
    const int qt = blockIdx.x;
    const int bh = blockIdx.y;
    const int b = bh >> 4, h = bh & 15;
    const int z = blockIdx.z;

    const float* Q = g_Q + (size_t)z * STREAM;
    const float* K = g_K + (size_t)(1 - z) * STREAM;
    const float* V = g_V + (size_t)(1 - z) * STREAM;
    float*       O = g_att + (size_t)z * STREAM;

    const int q0 = qt * 64;
    const size_t baseBH = (size_t)b * SA * HID + (size_t)h * HD;

    for (int t = tid; t < 64 * 16; t += 256) {
        int r = t >> 4, c4 = (t & 15) * 4;
        float4 v = make_float4(0.f, 0.f, 0.f, 0.f);
        if (q0 + r < SA) v = *(const float4*)&Q[baseBH + (size_t)(q0 + r) * HID + c4];
        *(float4*)&Qs[r * APAD + c4] = v;
    }

    float acc[4][4];
#pragma unroll
    for (int i = 0; i < 4; i++)
#pragma unroll
        for (int j = 0; j < 4; j++) acc[i][j] = 0.f;
    float mrow[4], lrow[4];
#pragma unroll
    for (int i = 0; i < 4; i++) { mrow[i] = -INFINITY; lrow[i] = 0.f; }

    __syncthreads();

    for (int k0 = 0; k0 < SA; k0 += 64) {
        for (int t = tid; t < 64 * 16; t += 256) {
            int r = t >> 4, c4 = (t & 15) * 4;
            float4 kv = make_float4(0.f, 0.f, 0.f, 0.f);
            float4 vv = kv;
            if (k0 + r < SA) {
                size_t g = baseBH + (size_t)(k0 + r) * HID + c4;
                kv = *(const float4*)&K[g];
                vv = *(const float4*)&V[g];
            }
            *(float4*)&Ks[r * APAD + c4] = kv;
            *(float4*)&Vs[r * APAD + c4] = vv;
        }
        __syncthreads();

        float s[4][4];
#pragma unroll
        for (int i = 0; i < 4; i++)
#pragma unroll
            for (int j = 0; j < 4; j++) s[i][j] = 0.f;

#pragma unroll 4
        for (int d = 0; d < 64; d += 4) {
            float4 qv[4], kv[4];
#pragma unroll
            for (int i = 0; i < 4; i++) qv[i] = *(const float4*)&Qs[(ty * 4 + i) * APAD + d];
#pragma unroll
            for (int j = 0; j < 4; j++) kv[j] = *(const float4*)&Ks[(tx * 4 + j) * APAD + d];
#pragma unroll
            for (int i = 0; i < 4; i++)
#pragma unroll
                for (int j = 0; j < 4; j++)
                    s[i][j] += qv[i].x * kv[j].x + qv[i].y * kv[j].y +
                               qv[i].z * kv[j].z + qv[i].w * kv[j].w;
        }

        const int kleft = SA - k0;
#pragma unroll
        for (int j = 0; j < 4; j++) {
            bool valid = (tx * 4 + j) < kleft;
#pragma unroll
            for (int i = 0; i < 4; i++)
                s[i][j] = valid ? s[i][j] * 0.125f : -1e30f;
        }

        float corr[4];
#pragma unroll
        for (int i = 0; i < 4; i++) {
            float m = fmaxf(fmaxf(s[i][0], s[i][1]), fmaxf(s[i][2], s[i][3]));
#pragma unroll
            for (int msk = 8; msk >= 1; msk >>= 1)
                m = fmaxf(m, __shfl_xor_sync(0xffffffffu, m, msk));
            float mnew = fmaxf(mrow[i], m);
            corr[i] = __expf(mrow[i] - mnew);
            mrow[i] = mnew;
            float rs = 0.f;
#pragma unroll
            for (int j = 0; j < 4; j++) {
                float p = __expf(s[i][j] - mnew);
                s[i][j] = p;
                rs += p;
            }
#pragma unroll
            for (int msk = 8; msk >= 1; msk >>= 1)
                rs += __shfl_xor_sync(0xffffffffu, rs, msk);
            lrow[i] = lrow[i] * corr[i] + rs;
        }

        __syncthreads();
#pragma unroll
        for (int i = 0; i < 4; i++)
            *(float4*)&Ks[(ty * 4 + i) * APAD + tx * 4] =
                make_float4(s[i][0], s[i][1], s[i][2], s[i][3]);
        __syncthreads();

#pragma unroll
        for (int i = 0; i < 4; i++)
#pragma unroll
            for (int j = 0; j < 4; j++) acc[i][j] *= corr[i];

#pragma unroll 4
        for (int k = 0; k < 64; k += 4) {
            float4 p4[4];
#pragma unroll
            for (int i = 0; i < 4; i++) p4[i] = *(const float4*)&Ks[(ty * 4 + i) * APAD + k];
            float4 v0 = *(const float4*)&Vs[(k + 0) * APAD + tx * 4];
            float4 v1 = *(const float4*)&Vs[(k + 1) * APAD + tx * 4];
            float4 v2 = *(const float4*)&Vs[(k + 2) * APAD + tx * 4];
            float4 v3 = *(const float4*)&Vs[(k + 3) * APAD + tx * 4];
#pragma unroll
            for (int i = 0; i < 4; i++) {
                acc[i][0] += p4[i].x * v0.x + p4[i].y * v1.x + p4[i].z * v2.x + p4[i].w * v3.x;
                acc[i][1] += p4[i].x * v0.y + p4[i].y * v1.y + p4[i].z * v2.y + p4[i].w * v3.y;
                acc[i][2] += p4[i].x * v0.z + p4[i].y * v1.z + p4[i].z * v2.z + p4[i].w * v3.z;
                acc[i][3] += p4[i].x * v0.w + p4[i].y * v1.w + p4[i].z * v2.w + p4[i].w * v3.w;
            }
        }
        __syncthreads();
    }

#pragma unroll
    for (int i = 0; i < 4; i++) {
        int qr = q0 + ty * 4 + i;
        if (qr < SA) {
            float inv = 1.0f / lrow[i];
            float4 o = make_float4(acc[i][0] * inv, acc[i][1] * inv,
                                   acc[i][2] * inv, acc[i][3] * inv);
            *(float4*)&O[baseBH + (size_t)qr * HID + tx * 4] = o;
        }
    }
}

// ---------------- residual + LayerNorm + slice -> output ----------------
__global__ __launch_bounds__(128) void ln_out_kernel(
    const float* __restrict__ gamma, const float* __restrict__ beta,
    float* __restrict__ out) {
    __shared__ float sbuf[4];
    const int row = blockIdx.x;
    const int c = row >> 12;
    const int r = row & 4095;
    const int b = r >> 11;
    const int s = r & 2047;
    const float* aug  = g_aug + (size_t)c * STREAM;
    const float* proj = g_Q   + (size_t)c * STREAM;   // out-proj results live here
    const size_t base = ((size_t)b * SA + s) * HID;
    const int tid = threadIdx.x;

    float x[8];
    float4 a0 = *(const float4*)&aug[base + tid * 8];
    float4 a1 = *(const float4*)&aug[base + tid * 8 + 4];
    float4 p0 = *(const float4*)&proj[base + tid * 8];
    float4 p1 = *(const float4*)&proj[base + tid * 8 + 4];
    x[0] = a0.x + p0.x; x[1] = a0.y + p0.y; x[2] = a0.z + p0.z; x[3] = a0.w + p0.w;
    x[4] = a1.x + p1.x; x[5] = a1.y + p1.y; x[6] = a1.z + p1.z; x[7] = a1.w + p1.w;

    float sum = 0.f;
#pragma unroll
    for (int j = 0; j < 8; j++) sum += x[j];
#pragma unroll
    for (int m = 16; m >= 1; m >>= 1) sum += __shfl_xor_sync(0xffffffffu, sum, m);
    if ((tid & 31) == 0) sbuf[tid >> 5] = sum;
    __syncthreads();
    float mu = (sbuf[0] + sbuf[1] + sbuf[2] + sbuf[3]) * (1.0f / HID);
    __syncthreads();

    float vs = 0.f;
#pragma unroll
    for (int j = 0; j < 8; j++) { float d = x[j] - mu; vs += d * d; }
#pragma unroll
    for (int m = 16; m >= 1; m >>= 1) vs += __shfl_xor_sync(0xffffffffu, vs, m);
    if ((tid & 31) == 0) sbuf[tid >> 5] = vs;
    __syncthreads();
    float var = (sbuf[0] + sbuf[1] + sbuf[2] + sbuf[3]) * (1.0f / HID);
    float rstd = rsqrtf(var + 1e-5f);

    float* op = out + (size_t)c * (BB * SS * HID) + ((size_t)b * SS + s) * HID + tid * 8;
    float o[8];
#pragma unroll
    for (int j = 0; j < 8; j++) {
        int col = tid * 8 + j;
        o[j] = (x[j] - mu) * rstd * gamma[col] + beta[col];
    }
    *(float4*)(op)     = make_float4(o[0], o[1], o[2], o[3]);
    *(float4*)(op + 4) = make_float4(o[4], o[5], o[6], o[7]);
}

// ---------------- launch ----------------
extern "C" void kernel_launch(void* const* d_in, const int* in_sizes, int n_in,
                              void* d_out, int out_size) {
    const float* cnn      = (const float*)d_in[0];
    const float* llm      = (const float*)d_in[1];
    const float* Wq       = (const float*)d_in[2];
    const float* bq       = (const float*)d_in[3];
    const float* Wk       = (const float*)d_in[4];
    const float* bk       = (const float*)d_in[5];
    const float* Wv       = (const float*)d_in[6];
    const float* bv       = (const float*)d_in[7];
    const float* Wo       = (const float*)d_in[8];
    const float* bo       = (const float*)d_in[9];
    const float* energy   = (const float*)d_in[10];
    const float* mass     = (const float*)d_in[11];
    const float* momentum = (const float*)d_in[12];
    const float* gamma    = (const float*)d_in[13];
    const float* beta     = (const float*)d_in[14];
    float* out = (float*)d_out;

    float *augP, *qP, *kP, *vP, *attP;
    cudaGetSymbolAddress((void**)&augP, g_aug);
    cudaGetSymbolAddress((void**)&qP,   g_Q);
    cudaGetSymbolAddress((void**)&kP,   g_K);
    cudaGetSymbolAddress((void**)&vP,   g_V);
    cudaGetSymbolAddress((void**)&attP, g_att);

    const int tot4 = BB * SA * HID / 4;
    build_aug_kernel<<<(tot4 + 255) / 256, 256>>>(cnn, llm, energy, mass, momentum);

    cudaFuncSetAttribute(gemm_mma_kernel, cudaFuncAttributeMaxDynamicSharedMemorySize, GEMM_SMEM);
    dim3 ggrid(HID / TN, (MTOT2 + TM - 1) / TM);   // (8, 65)
    gemm_mma_kernel<<<ggrid, 256, GEMM_SMEM>>>(augP, Wq, bq, qP, MTOT2);
    gemm_mma_kernel<<<ggrid, 256, GEMM_SMEM>>>(augP, Wk, bk, kP, MTOT2);
    gemm_mma_kernel<<<ggrid, 256, GEMM_SMEM>>>(augP, Wv, bv, vP, MTOT2);

    const int smem = 3 * 64 * APAD * 4;   // 52224 B
    cudaFuncSetAttribute(attn_kernel, cudaFuncAttributeMaxDynamicSharedMemorySize, smem);
    dim3 agrid((SA + 63) / 64, BB * NH, 2);
    attn_kernel<<<agrid, 256, smem>>>();

    // output projection for both streams in one GEMM (result reuses g_Q)
    gemm_mma_kernel<<<ggrid, 256, GEMM_SMEM>>>(attP, Wo, bo, qP, MTOT2);

    ln_out_kernel<<<2 * BB * SS, 128>>>(gamma, beta, out);
}

// round 4
// speedup vs baseline: 2.5781x; 2.1428x over previous
#include <cuda_runtime.h>
#include <cuda_bf16.h>
#include <math.h>
#include <cstdint>

#define BB 2
#define SS 2048
#define SA 2051            // S + 3 physics tokens
#define HID 1024
#define NH 16
#define HD 64
#define STREAM (BB*SA*HID) // floats per stream
#define MTOT2 (2*BB*SA)    // 8204 merged rows

// ---------------- GEMM (mma.sync bf16, split) tiling ----------------
#define TM 128
#define TN 128
#define KC 32
#define NCHUNK (HID/KC)    // 32
#define A_STR 80
#define B_STR 272
#define SM_AHI 0
#define SM_ALO (128*A_STR)
#define SM_BHI (2*128*A_STR)
#define SM_BLO (SM_BHI + 32*B_STR)
#define GEMM_SMEM (SM_BLO + 32*B_STR) // 37888

#define SWZ(o) ((o) ^ (((o) >> 3) & 0x70))

// attention smem offsets (32KB total, all 8KB-aligned)
#define AT_KH 0
#define AT_KL 8192
#define AT_VH 16384
#define AT_VL 24576
#define AT_QH 0
#define AT_QL 16384
#define ATTN_SMEM 32768

// ---------------- device scratch (no allocations allowed) ----------------
__device__ float g_aug[2*STREAM];
__device__ float g_Q[2*STREAM];
__device__ float g_K[2*STREAM];
__device__ float g_V[2*STREAM];
__device__ float g_att[2*STREAM];

// ---------------- helpers ----------------
__device__ __forceinline__ uint32_t smem_u32(const void* p) {
    uint32_t a;
    asm("{ .reg .u64 t; cvta.to.shared.u64 t, %1; cvt.u32.u64 %0, t; }" : "=r"(a) : "l"(p));
    return a;
}
__device__ __forceinline__ void mma16816(float* d, const uint32_t* a, const uint32_t* b) {
    asm volatile(
        "mma.sync.aligned.m16n8k16.row.col.f32.bf16.bf16.f32 "
        "{%0,%1,%2,%3}, {%4,%5,%6,%7}, {%8,%9}, {%0,%1,%2,%3};"
        : "+f"(d[0]), "+f"(d[1]), "+f"(d[2]), "+f"(d[3])
        : "r"(a[0]), "r"(a[1]), "r"(a[2]), "r"(a[3]), "r"(b[0]), "r"(b[1]));
}
__device__ __forceinline__ void ldmx4(uint32_t* r, uint32_t addr) {
    asm volatile("ldmatrix.sync.aligned.m8n8.x4.shared.b16 {%0,%1,%2,%3}, [%4];"
                 : "=r"(r[0]), "=r"(r[1]), "=r"(r[2]), "=r"(r[3]) : "r"(addr));
}
__device__ __forceinline__ void ldmx4t(uint32_t* r, uint32_t addr) {
    asm volatile("ldmatrix.sync.aligned.m8n8.x4.trans.shared.b16 {%0,%1,%2,%3}, [%4];"
                 : "=r"(r[0]), "=r"(r[1]), "=r"(r[2]), "=r"(r[3]) : "r"(addr));
}
__device__ __forceinline__ uint32_t pk_bf2(__nv_bfloat16 a, __nv_bfloat16 b) {
    __nv_bfloat162 t(a, b);
    return *reinterpret_cast<uint32_t*>(&t);
}
__device__ __forceinline__ void split2(float f, __nv_bfloat16& h, __nv_bfloat16& l) {
    h = __float2bfloat16(f);
    l = __float2bfloat16(f - __bfloat162float(h));
}
__device__ __forceinline__ void split8(float4 v0, float4 v1, uint4& hi, uint4& lo) {
    __nv_bfloat16 h[8], l[8];
    float f[8] = {v0.x, v0.y, v0.z, v0.w, v1.x, v1.y, v1.z, v1.w};
#pragma unroll
    for (int j = 0; j < 8; j++) split2(f[j], h[j], l[j]);
    hi = make_uint4(pk_bf2(h[0], h[1]), pk_bf2(h[2], h[3]), pk_bf2(h[4], h[5]), pk_bf2(h[6], h[7]));
    lo = make_uint4(pk_bf2(l[0], l[1]), pk_bf2(l[2], l[3]), pk_bf2(l[4], l[5]), pk_bf2(l[6], l[7]));
}

// ---------------- build augmented sequences ----------------
__global__ void build_aug_kernel(const float* __restrict__ cnn,
                                 const float* __restrict__ llm,
                                 const float* __restrict__ energy,
                                 const float* __restrict__ mass,
                                 const float* __restrict__ momentum) {
    int idx = blockIdx.x * blockDim.x + threadIdx.x;
    const int total = BB * SA * HID / 4;
    if (idx >= total) return;
    int h4  = idx % (HID / 4);
    int row = idx / (HID / 4);
    int s   = row % SA;
    int b   = row / SA;
    float4 vC, vL;
    if (s < SS) {
        vC = ((const float4*)cnn)[(size_t)(b * SS + s) * (HID / 4) + h4];
        vL = ((const float4*)llm)[(size_t)(b * SS + s) * (HID / 4) + h4];
    } else {
        const float* e = (s == SS) ? energy : ((s == SS + 1) ? mass : momentum);
        vC = ((const float4*)e)[h4];
        vL = vC;
    }
    ((float4*)g_aug)[idx] = vC;
    ((float4*)g_aug)[idx + STREAM / 4] = vL;
}

// ---------------- tensor-core GEMM (unchanged from R3, verified) ----------------
__global__ __launch_bounds__(256, 1) void gemm_mma_kernel(
    const float* __restrict__ A, const float* __restrict__ W,
    const float* __restrict__ bias, float* __restrict__ C, int M) {
    extern __shared__ char smc[];
    const uint32_t sb = smem_u32(smc);
    const int tid = threadIdx.x, lane = tid & 31, wid = tid >> 5;
    const int wm = wid >> 2, wn = wid & 3;
    const int row0 = blockIdx.y * TM, col0 = blockIdx.x * TN;

    const int arow = tid >> 1, acol = (tid & 1) * 16;
    const int bk = tid >> 3, bn = (tid & 7) * 16;
    const bool a_ok = (row0 + arow) < M;
    const float* Ag = A + (size_t)(row0 + arow) * HID + acol;
    const float* Wg = W + (size_t)bk * HID + col0 + bn;

    float pa[16], pb[16];
#pragma unroll
    for (int i = 0; i < 4; i++) {
        float4 v = a_ok ? *(const float4*)(Ag + i * 4) : make_float4(0.f, 0.f, 0.f, 0.f);
        pa[4*i] = v.x; pa[4*i+1] = v.y; pa[4*i+2] = v.z; pa[4*i+3] = v.w;
        float4 w = *(const float4*)(Wg + i * 4);
        pb[4*i] = w.x; pb[4*i+1] = w.y; pb[4*i+2] = w.z; pb[4*i+3] = w.w;
    }

    float acc[4][4][4];
#pragma unroll
    for (int i = 0; i < 4; i++)
#pragma unroll
        for (int j = 0; j < 4; j++)
#pragma unroll
            for (int k = 0; k < 4; k++) acc[i][j][k] = 0.f;

    const uint32_t a_lane = (uint32_t)((lane & 15) * A_STR + (lane >> 4) * 16);
    const uint32_t b_lane = (uint32_t)(((((lane >> 3) & 1) * 8) + (lane & 7)) * B_STR
                                       + (lane >> 4) * 16);

    for (int ch = 0; ch < NCHUNK; ch++) {
        {
            uint32_t h[8], l[8];
#pragma unroll
            for (int j = 0; j < 8; j++) {
                __nv_bfloat16 h0, l0, h1, l1;
                split2(pa[2*j], h0, l0); split2(pa[2*j+1], h1, l1);
                h[j] = pk_bf2(h0, h1); l[j] = pk_bf2(l0, l1);
            }
            char* ab = smc + arow * A_STR + acol * 2;
            *(uint4*)(ab + SM_AHI)      = make_uint4(h[0], h[1], h[2], h[3]);
            *(uint4*)(ab + SM_AHI + 16) = make_uint4(h[4], h[5], h[6], h[7]);
            *(uint4*)(ab + SM_ALO)      = make_uint4(l[0], l[1], l[2], l[3]);
            *(uint4*)(ab + SM_ALO + 16) = make_uint4(l[4], l[5], l[6], l[7]);
#pragma unroll
            for (int j = 0; j < 8; j++) {
                __nv_bfloat16 h0, l0, h1, l1;
                split2(pb[2*j], h0, l0); split2(pb[2*j+1], h1, l1);
                h[j] = pk_bf2(h0, h1); l[j] = pk_bf2(l0, l1);
            }
            char* bb = smc + bk * B_STR + bn * 2;
            *(uint4*)(bb + SM_BHI)      = make_uint4(h[0], h[1], h[2], h[3]);
            *(uint4*)(bb + SM_BHI + 16) = make_uint4(h[4], h[5], h[6], h[7]);
            *(uint4*)(bb + SM_BLO)      = make_uint4(l[0], l[1], l[2], l[3]);
            *(uint4*)(bb + SM_BLO + 16) = make_uint4(l[4], l[5], l[6], l[7]);
        }
        __syncthreads();

        if (ch + 1 < NCHUNK) {
            const float* ap = Ag + (ch + 1) * KC;
            const float* wp = Wg + (size_t)(ch + 1) * KC * HID;
#pragma unroll
            for (int i = 0; i < 4; i++) {
                float4 v = a_ok ? *(const float4*)(ap + i * 4) : make_float4(0.f, 0.f, 0.f, 0.f);
                pa[4*i] = v.x; pa[4*i+1] = v.y; pa[4*i+2] = v.z; pa[4*i+3] = v.w;
                float4 w = *(const float4*)(wp + i * 4);
                pb[4*i] = w.x; pb[4*i+1] = w.y; pb[4*i+2] = w.z; pb[4*i+3] = w.w;
            }
        }

#pragma unroll
        for (int ks = 0; ks < 2; ks++) {
            uint32_t ahi[4][4], alo[4][4], bhi[4][2], blo[4][2];
#pragma unroll
            for (int mt = 0; mt < 4; mt++) {
                uint32_t ao = sb + (uint32_t)((wm * 64 + mt * 16) * A_STR + ks * 32) + a_lane;
                ldmx4(ahi[mt], ao + SM_AHI);
                ldmx4(alo[mt], ao + SM_ALO);
            }
            {
                uint32_t bo = sb + (uint32_t)(ks * 16 * B_STR + wn * 64) + b_lane;
                uint32_t t[4];
                ldmx4t(t, bo + SM_BHI);
                bhi[0][0]=t[0]; bhi[0][1]=t[1]; bhi[1][0]=t[2]; bhi[1][1]=t[3];
                ldmx4t(t, bo + SM_BHI + 32);
                bhi[2][0]=t[0]; bhi[2][1]=t[1]; bhi[3][0]=t[2]; bhi[3][1]=t[3];
                ldmx4t(t, bo + SM_BLO);
                blo[0][0]=t[0]; blo[0][1]=t[1]; blo[1][0]=t[2]; blo[1][1]=t[3];
                ldmx4t(t, bo + SM_BLO + 32);
                blo[2][0]=t[0]; blo[2][1]=t[1]; blo[3][0]=t[2]; blo[3][1]=t[3];
            }
#pragma unroll
            for (int mt = 0; mt < 4; mt++)
#pragma unroll
                for (int nt = 0; nt < 4; nt++) {
                    mma16816(acc[mt][nt], ahi[mt], bhi[nt]);
                    mma16816(acc[mt][nt], ahi[mt], blo[nt]);
                    mma16816(acc[mt][nt], alo[mt], bhi[nt]);
                }
        }
        __syncthreads();
    }

    const int mb = row0 + wm * 64 + (lane >> 2);
    const int nb = col0 + wn * 32 + (lane & 3) * 2;
#pragma unroll
    for (int nt = 0; nt < 4; nt++) {
        const int n = nb + nt * 8;
        const float2 bv = *(const float2*)&bias[n];
#pragma unroll
        for (int mt = 0; mt < 4; mt++) {
            const int m = mb + mt * 16;
            if (m < M)
                *(float2*)&C[(size_t)m * HID + n] =
                    make_float2(acc[mt][nt][0] + bv.x, acc[mt][nt][1] + bv.y);
            if (m + 8 < M)
                *(float2*)&C[(size_t)(m + 8) * HID + n] =
                    make_float2(acc[mt][nt][2] + bv.x, acc[mt][nt][3] + bv.y);
        }
    }
}

// ---------------- tensor-core flash cross-attention ----------------
// grid (17 q-tiles, 32 bh, 2 streams), 256 thr. Br=128 (16/warp), Bc=64, D=64.
// Per-row softmax biases are constant along k -> drop out of softmax exactly.
__global__ __launch_bounds__(256) void attn_mma_kernel() {
    extern __shared__ char smc[];
    const uint32_t sb = smem_u32(smc);
    const int tid = threadIdx.x, lane = tid & 31, wid = tid >> 5;
    const int qt = blockIdx.x, bh = blockIdx.y, z = blockIdx.z;
    const int b = bh >> 4, h = bh & 15;

    const float* Q = g_Q + (size_t)z * STREAM;
    const float* K = g_K + (size_t)(1 - z) * STREAM;
    const float* V = g_V + (size_t)(1 - z) * STREAM;
    float*       O = g_att + (size_t)z * STREAM;
    const size_t baseBH = (size_t)b * SA * HID + h * HD;
    const int q0 = qt * 128;

    // ---- stage Q tile [128 x 64] as split bf16 (swizzled) ----
    for (int idx = tid; idx < 128 * 8; idx += 256) {
        int r = idx >> 3, c8 = (idx & 7) * 8;
        float4 v0 = make_float4(0.f, 0.f, 0.f, 0.f), v1 = v0;
        if (q0 + r < SA) {
            const float* p = &Q[baseBH + (size_t)(q0 + r) * HID + c8];
            v0 = *(const float4*)p; v1 = *(const float4*)(p + 4);
        }
        uint4 hi, lo;
        split8(v0, v1, hi, lo);
        uint32_t off = SWZ((uint32_t)(r * 128 + c8 * 2));
        *(uint4*)(smc + AT_QH + off) = hi;
        *(uint4*)(smc + AT_QL + off) = lo;
    }
    __syncthreads();

    // per-warp Q a-frags (persistent)
    uint32_t qh[4][4], ql[4][4];
#pragma unroll
    for (int ks = 0; ks < 4; ks++) {
        uint32_t off = SWZ((uint32_t)((wid * 16 + (lane & 15)) * 128 + ks * 32 + (lane >> 4) * 16));
        ldmx4(qh[ks], sb + AT_QH + off);
        ldmx4(ql[ks], sb + AT_QL + off);
    }
    __syncthreads();   // done reading Q area; K/V will overwrite

    float o[8][4];
#pragma unroll
    for (int n = 0; n < 8; n++)
#pragma unroll
        for (int c = 0; c < 4; c++) o[n][c] = 0.f;
    float m0r = -INFINITY, m1r = -INFINITY, l0r = 0.f, l1r = 0.f;

    for (int k0 = 0; k0 < SA; k0 += 64) {
        // ---- cooperative load + split K,V tiles [64 x 64] ----
        for (int idx = tid; idx < 64 * 8; idx += 256) {
            int r = idx >> 3, c8 = (idx & 7) * 8;
            float4 k0v = make_float4(0.f, 0.f, 0.f, 0.f), k1v = k0v, v0v = k0v, v1v = k0v;
            if (k0 + r < SA) {
                const float* kp = &K[baseBH + (size_t)(k0 + r) * HID + c8];
                const float* vp = &V[baseBH + (size_t)(k0 + r) * HID + c8];
                k0v = *(const float4*)kp; k1v = *(const float4*)(kp + 4);
                v0v = *(const float4*)vp; v1v = *(const float4*)(vp + 4);
            }
            uint4 hi, lo;
            uint32_t off = SWZ((uint32_t)(r * 128 + c8 * 2));
            split8(k0v, k1v, hi, lo);
            *(uint4*)(smc + AT_KH + off) = hi;
            *(uint4*)(smc + AT_KL + off) = lo;
            split8(v0v, v1v, hi, lo);
            *(uint4*)(smc + AT_VH + off) = hi;
            *(uint4*)(smc + AT_VL + off) = lo;
        }
        __syncthreads();

        // ---- S = Q @ K^T (3 split terms) ----
        float s[8][4];
#pragma unroll
        for (int n = 0; n < 8; n++)
#pragma unroll
            for (int c = 0; c < 4; c++) s[n][c] = 0.f;

#pragma unroll
        for (int kt2 = 0; kt2 < 4; kt2++) {
#pragma unroll
            for (int ks = 0; ks < 4; ks++) {
                uint32_t off = SWZ((uint32_t)((kt2 * 16 + (lane & 15)) * 128 + ks * 32 + (lane >> 4) * 16));
                uint32_t kb[4], kl[4];
                ldmx4(kb, sb + AT_KH + off);
                ldmx4(kl, sb + AT_KL + off);
                uint32_t blo_h[2] = {kb[0], kb[2]}, bhi_h[2] = {kb[1], kb[3]};
                uint32_t blo_l[2] = {kl[0], kl[2]}, bhi_l[2] = {kl[1], kl[3]};
                mma16816(s[2*kt2],     qh[ks], blo_h);
                mma16816(s[2*kt2],     qh[ks], blo_l);
                mma16816(s[2*kt2],     ql[ks], blo_h);
                mma16816(s[2*kt2 + 1], qh[ks], bhi_h);
                mma16816(s[2*kt2 + 1], qh[ks], bhi_l);
                mma16816(s[2*kt2 + 1], ql[ks], bhi_h);
            }
        }

        // ---- scale + mask ----
#pragma unroll
        for (int n = 0; n < 8; n++)
#pragma unroll
            for (int c = 0; c < 4; c++) s[n][c] *= 0.125f;
        if (k0 + 64 > SA) {
#pragma unroll
            for (int n = 0; n < 8; n++) {
                int ktc = k0 + (n >> 1) * 16 + (n & 1) * 8 + (lane & 3) * 2;
#pragma unroll
                for (int c = 0; c < 4; c++)
                    if (ktc + (c & 1) >= SA) s[n][c] = -1e30f;
            }
        }

        // ---- online softmax (thread owns 2 rows: r, r+8) ----
        float mx0 = -INFINITY, mx1 = -INFINITY;
#pragma unroll
        for (int n = 0; n < 8; n++) {
            mx0 = fmaxf(mx0, fmaxf(s[n][0], s[n][1]));
            mx1 = fmaxf(mx1, fmaxf(s[n][2], s[n][3]));
        }
#pragma unroll
        for (int msk = 1; msk <= 2; msk <<= 1) {
            mx0 = fmaxf(mx0, __shfl_xor_sync(0xffffffffu, mx0, msk));
            mx1 = fmaxf(mx1, __shfl_xor_sync(0xffffffffu, mx1, msk));
        }
        float mn0 = fmaxf(m0r, mx0), mn1 = fmaxf(m1r, mx1);
        float c0 = __expf(m0r - mn0), c1 = __expf(m1r - mn1);
        m0r = mn0; m1r = mn1;
        float rs0 = 0.f, rs1 = 0.f;
#pragma unroll
        for (int n = 0; n < 8; n++) {
            s[n][0] = __expf(s[n][0] - mn0); rs0 += s[n][0];
            s[n][1] = __expf(s[n][1] - mn0); rs0 += s[n][1];
            s[n][2] = __expf(s[n][2] - mn1); rs1 += s[n][2];
            s[n][3] = __expf(s[n][3] - mn1); rs1 += s[n][3];
        }
#pragma unroll
        for (int msk = 1; msk <= 2; msk <<= 1) {
            rs0 += __shfl_xor_sync(0xffffffffu, rs0, msk);
            rs1 += __shfl_xor_sync(0xffffffffu, rs1, msk);
        }
        l0r = l0r * c0 + rs0;
        l1r = l1r * c1 + rs1;
#pragma unroll
        for (int n = 0; n < 8; n++) {
            o[n][0] *= c0; o[n][1] *= c0; o[n][2] *= c1; o[n][3] *= c1;
        }

        // ---- pack P (split) into a-frags directly from S registers ----
        uint32_t pah[4][4], pal[4][4];
#pragma unroll
        for (int ks = 0; ks < 4; ks++) {
            const int j0 = 2 * ks, j1 = 2 * ks + 1;
            __nv_bfloat16 hh[8], ll[8];
            split2(s[j0][0], hh[0], ll[0]); split2(s[j0][1], hh[1], ll[1]);
            split2(s[j0][2], hh[2], ll[2]); split2(s[j0][3], hh[3], ll[3]);
            split2(s[j1][0], hh[4], ll[4]); split2(s[j1][1], hh[5], ll[5]);
            split2(s[j1][2], hh[6], ll[6]); split2(s[j1][3], hh[7], ll[7]);
            pah[ks][0] = pk_bf2(hh[0], hh[1]); pah[ks][1] = pk_bf2(hh[2], hh[3]);
            pah[ks][2] = pk_bf2(hh[4], hh[5]); pah[ks][3] = pk_bf2(hh[6], hh[7]);
            pal[ks][0] = pk_bf2(ll[0], ll[1]); pal[ks][1] = pk_bf2(ll[2], ll[3]);
            pal[ks][2] = pk_bf2(ll[4], ll[5]); pal[ks][3] = pk_bf2(ll[6], ll[7]);
        }

        // ---- O += P @ V (3 split terms), V^T frags via trans ldmatrix ----
        const uint32_t rp = ((lane >> 3) & 1) * 8 + (lane & 7);
#pragma unroll
        for (int dt = 0; dt < 4; dt++) {
#pragma unroll
            for (int ks = 0; ks < 4; ks++) {
                uint32_t off = SWZ((uint32_t)((ks * 16 + rp) * 128 + dt * 32 + (lane >> 4) * 16));
                uint32_t vb[4], vl[4];
                ldmx4t(vb, sb + AT_VH + off);
                ldmx4t(vl, sb + AT_VL + off);
                uint32_t b0h[2] = {vb[0], vb[1]}, b1h[2] = {vb[2], vb[3]};
                uint32_t b0l[2] = {vl[0], vl[1]}, b1l[2] = {vl[2], vl[3]};
                mma16816(o[2*dt],     pah[ks], b0h);
                mma16816(o[2*dt],     pah[ks], b0l);
                mma16816(o[2*dt],     pal[ks], b0h);
                mma16816(o[2*dt + 1], pah[ks], b1h);
                mma16816(o[2*dt + 1], pah[ks], b1l);
                mma16816(o[2*dt + 1], pal[ks], b1h);
            }
        }
        __syncthreads();   // before next tile overwrites K/V smem
    }

    // ---- epilogue: normalize, store ----
    const int r0 = q0 + wid * 16 + (lane >> 2);
    const float inv0 = 1.0f / l0r, inv1 = 1.0f / l1r;
#pragma unroll
    for (int n = 0; n < 8; n++) {
        const int col = (n >> 1) * 16 + (n & 1) * 8 + (lane & 3) * 2;
        if (r0 < SA)
            *(float2*)&O[baseBH + (size_t)r0 * HID + col] =
                make_float2(o[n][0] * inv0, o[n][1] * inv0);
        if (r0 + 8 < SA)
            *(float2*)&O[baseBH + (size_t)(r0 + 8) * HID + col] =
                make_float2(o[n][2] * inv1, o[n][3] * inv1);
    }
}

// ---------------- residual + LayerNorm + slice -> output ----------------
__global__ __launch_bounds__(128) void ln_out_kernel(
    const float* __restrict__ gamma, const float* __restrict__ beta,
    float* __restrict__ out) {
    __shared__ float sbuf[4];
    const int row = blockIdx.x;
    const int c = row >> 12;
    const int r = row & 4095;
    const int b = r >> 11;
    const int s = r & 2047;
    const float* aug  = g_aug + (size_t)c * STREAM;
    const float* proj = g_Q   + (size_t)c * STREAM;
    const size_t base = ((size_t)b * SA + s) * HID;
    const int tid = threadIdx.x;

    float x[8];
    float4 a0 = *(const float4*)&aug[base + tid * 8];
    float4 a1 = *(const float4*)&aug[base + tid * 8 + 4];
    float4 p0 = *(const float4*)&proj[base + tid * 8];
    float4 p1 = *(const float4*)&proj[base + tid * 8 + 4];
    x[0] = a0.x + p0.x; x[1] = a0.y + p0.y; x[2] = a0.z + p0.z; x[3] = a0.w + p0.w;
    x[4] = a1.x + p1.x; x[5] = a1.y + p1.y; x[6] = a1.z + p1.z; x[7] = a1.w + p1.w;

    float sum = 0.f;
#pragma unroll
    for (int j = 0; j < 8; j++) sum += x[j];
#pragma unroll
    for (int m = 16; m >= 1; m >>= 1) sum += __shfl_xor_sync(0xffffffffu, sum, m);
    if ((tid & 31) == 0) sbuf[tid >> 5] = sum;
    __syncthreads();
    float mu = (sbuf[0] + sbuf[1] + sbuf[2] + sbuf[3]) * (1.0f / HID);
    __syncthreads();

    float vs = 0.f;
#pragma unroll
    for (int j = 0; j < 8; j++) { float d = x[j] - mu; vs += d * d; }
#pragma unroll
    for (int m = 16; m >= 1; m >>= 1) vs += __shfl_xor_sync(0xffffffffu, vs, m);
    if ((tid & 31) == 0) sbuf[tid >> 5] = vs;
    __syncthreads();
    float var = (sbuf[0] + sbuf[1] + sbuf[2] + sbuf[3]) * (1.0f / HID);
    float rstd = rsqrtf(var + 1e-5f);

    float* op = out + (size_t)c * (BB * SS * HID) + ((size_t)b * SS + s) * HID + tid * 8;
    float o[8];
#pragma unroll
    for (int j = 0; j < 8; j++) {
        int col = tid * 8 + j;
        o[j] = (x[j] - mu) * rstd * gamma[col] + beta[col];
    }
    *(float4*)(op)     = make_float4(o[0], o[1], o[2], o[3]);
    *(float4*)(op + 4) = make_float4(o[4], o[5], o[6], o[7]);
}

// ---------------- launch ----------------
extern "C" void kernel_launch(void* const* d_in, const int* in_sizes, int n_in,
                              void* d_out, int out_size) {
    const float* cnn      = (const float*)d_in[0];
    const float* llm      = (const float*)d_in[1];
    const float* Wq       = (const float*)d_in[2];
    const float* bq       = (const float*)d_in[3];
    const float* Wk       = (const float*)d_in[4];
    const float* bk       = (const float*)d_in[5];
    const float* Wv       = (const float*)d_in[6];
    const float* bv       = (const float*)d_in[7];
    const float* Wo       = (const float*)d_in[8];
    const float* bo       = (const float*)d_in[9];
    const float* energy   = (const float*)d_in[10];
    const float* mass     = (const float*)d_in[11];
    const float* momentum = (const float*)d_in[12];
    const float* gamma    = (const float*)d_in[13];
    const float* beta     = (const float*)d_in[14];
    float* out = (float*)d_out;

    float *augP, *qP, *kP, *vP, *attP;
    cudaGetSymbolAddress((void**)&augP, g_aug);
    cudaGetSymbolAddress((void**)&qP,   g_Q);
    cudaGetSymbolAddress((void**)&kP,   g_K);
    cudaGetSymbolAddress((void**)&vP,   g_V);
    cudaGetSymbolAddress((void**)&attP, g_att);

    const int tot4 = BB * SA * HID / 4;
    build_aug_kernel<<<(tot4 + 255) / 256, 256>>>(cnn, llm, energy, mass, momentum);

    cudaFuncSetAttribute(gemm_mma_kernel, cudaFuncAttributeMaxDynamicSharedMemorySize, GEMM_SMEM);
    dim3 ggrid(HID / TN, (MTOT2 + TM - 1) / TM);   // (8, 65)
    gemm_mma_kernel<<<ggrid, 256, GEMM_SMEM>>>(augP, Wq, bq, qP, MTOT2);
    gemm_mma_kernel<<<ggrid, 256, GEMM_SMEM>>>(augP, Wk, bk, kP, MTOT2);
    gemm_mma_kernel<<<ggrid, 256, GEMM_SMEM>>>(augP, Wv, bv, vP, MTOT2);

    cudaFuncSetAttribute(attn_mma_kernel, cudaFuncAttributeMaxDynamicSharedMemorySize, ATTN_SMEM);
    dim3 agrid((SA + 127) / 128, BB * NH, 2);      // (17, 32, 2)
    attn_mma_kernel<<<agrid, 256, ATTN_SMEM>>>();

    gemm_mma_kernel<<<ggrid, 256, GEMM_SMEM>>>(attP, Wo, bo, qP, MTOT2);

    ln_out_kernel<<<2 * BB * SS, 128>>>(gamma, beta, out);
}

// round 5
// speedup vs baseline: 3.3592x; 1.3030x over previous
#include <cuda_runtime.h>
#include <cuda_bf16.h>
#include <math.h>
#include <cstdint>

#define BB 2
#define SS 2048
#define SA 2051            // S + 3 physics tokens
#define HID 1024
#define NH 16
#define HD 64
#define STREAM (BB*SA*HID) // elems per stream
#define MTOT2 (2*BB*SA)    // 8204 merged rows

#define SWZ(o) ((o) ^ (((o) >> 3) & 0x70))

// ---------------- GEMM v2 tiling ----------------
#define TM 128
#define TN 128
#define KC2 64
#define NCH2 (HID/KC2)     // 16
#define A_STR2 144         // 128B data + 16 pad
#define B_STR2 272         // 256B data + 16 pad
#define SA_HI 0
#define SA_LO (128*A_STR2)           // 18432
#define SB_HI (2*128*A_STR2)         // 36864
#define SB_LO (SB_HI + 64*B_STR2)    // 54272
#define STG2  (SB_LO + 64*B_STR2)    // 71680
#define GEMM2_SMEM (2*STG2)          // 143360

// ---------------- attention v2 smem ----------------
#define AT2_KH 0
#define AT2_KL 8192
#define AT2_VH 16384
#define AT2_VL 24576
#define AT2_STG 32768
#define ATTN2_SMEM (2*AT2_STG)       // 65536

// ---------------- device scratch ----------------
__device__ float g_aug[2*STREAM];            // fp32 residual
__device__ float g_proj[2*STREAM];           // out-proj fp32 result
__device__ __nv_bfloat16 g_augH[2*STREAM], g_augL[2*STREAM];
__device__ __nv_bfloat16 g_QH[2*STREAM], g_QL[2*STREAM];
__device__ __nv_bfloat16 g_KH[2*STREAM], g_KL[2*STREAM];
__device__ __nv_bfloat16 g_VH[2*STREAM], g_VL[2*STREAM];
__device__ __nv_bfloat16 g_attH[2*STREAM], g_attL[2*STREAM];
__device__ __nv_bfloat16 g_WH[4*HID*HID], g_WL[4*HID*HID];

// ---------------- helpers ----------------
__device__ __forceinline__ uint32_t smem_u32(const void* p) {
    uint32_t a;
    asm("{ .reg .u64 t; cvta.to.shared.u64 t, %1; cvt.u32.u64 %0, t; }" : "=r"(a) : "l"(p));
    return a;
}
__device__ __forceinline__ void mma16816(float* d, const uint32_t* a, const uint32_t* b) {
    asm volatile(
        "mma.sync.aligned.m16n8k16.row.col.f32.bf16.bf16.f32 "
        "{%0,%1,%2,%3}, {%4,%5,%6,%7}, {%8,%9}, {%0,%1,%2,%3};"
        : "+f"(d[0]), "+f"(d[1]), "+f"(d[2]), "+f"(d[3])
        : "r"(a[0]), "r"(a[1]), "r"(a[2]), "r"(a[3]), "r"(b[0]), "r"(b[1]));
}
__device__ __forceinline__ void ldmx4(uint32_t* r, uint32_t addr) {
    asm volatile("ldmatrix.sync.aligned.m8n8.x4.shared.b16 {%0,%1,%2,%3}, [%4];"
                 : "=r"(r[0]), "=r"(r[1]), "=r"(r[2]), "=r"(r[3]) : "r"(addr));
}
__device__ __forceinline__ void ldmx4t(uint32_t* r, uint32_t addr) {
    asm volatile("ldmatrix.sync.aligned.m8n8.x4.trans.shared.b16 {%0,%1,%2,%3}, [%4];"
                 : "=r"(r[0]), "=r"(r[1]), "=r"(r[2]), "=r"(r[3]) : "r"(addr));
}
__device__ __forceinline__ void cpasync16(uint32_t dst, const void* src, int sz) {
    asm volatile("cp.async.cg.shared.global [%0], [%1], 16, %2;"
                 :: "r"(dst), "l"(src), "r"(sz));
}
__device__ __forceinline__ void cpcommit() { asm volatile("cp.async.commit_group;" ::: "memory"); }
template<int N> __device__ __forceinline__ void cpwait() {
    asm volatile("cp.async.wait_group %0;" :: "n"(N) : "memory");
}
__device__ __forceinline__ uint32_t pk_bf2(__nv_bfloat16 a, __nv_bfloat16 b) {
    __nv_bfloat162 t(a, b);
    return *reinterpret_cast<uint32_t*>(&t);
}
__device__ __forceinline__ void split2(float f, __nv_bfloat16& h, __nv_bfloat16& l) {
    h = __float2bfloat16(f);
    l = __float2bfloat16(f - __bfloat162float(h));
}
__device__ __forceinline__ void split8(float4 v0, float4 v1, uint4& hi, uint4& lo) {
    __nv_bfloat16 h[8], l[8];
    float f[8] = {v0.x, v0.y, v0.z, v0.w, v1.x, v1.y, v1.z, v1.w};
#pragma unroll
    for (int j = 0; j < 8; j++) split2(f[j], h[j], l[j]);
    hi = make_uint4(pk_bf2(h[0], h[1]), pk_bf2(h[2], h[3]), pk_bf2(h[4], h[5]), pk_bf2(h[6], h[7]));
    lo = make_uint4(pk_bf2(l[0], l[1]), pk_bf2(l[2], l[3]), pk_bf2(l[4], l[5]), pk_bf2(l[6], l[7]));
}

// ---------------- build augmented sequences (fp32 + split bf16) ----------------
__global__ void build_aug_kernel(const float* __restrict__ cnn,
                                 const float* __restrict__ llm,
                                 const float* __restrict__ energy,
                                 const float* __restrict__ mass,
                                 const float* __restrict__ momentum) {
    int idx = blockIdx.x * blockDim.x + threadIdx.x;   // 8-float unit
    const int total = BB * SA * HID / 8;
    if (idx >= total) return;
    int h8  = idx % (HID / 8);
    int row = idx / (HID / 8);
    int s   = row % SA;
    int b   = row / SA;
    float4 c0, c1, l0, l1;
    if (s < SS) {
        const float* cp = cnn + ((size_t)(b * SS + s) * HID) + h8 * 8;
        const float* lp = llm + ((size_t)(b * SS + s) * HID) + h8 * 8;
        c0 = *(const float4*)cp; c1 = *(const float4*)(cp + 4);
        l0 = *(const float4*)lp; l1 = *(const float4*)(lp + 4);
    } else {
        const float* e = (s == SS) ? energy : ((s == SS + 1) ? mass : momentum);
        c0 = *(const float4*)(e + h8 * 8); c1 = *(const float4*)(e + h8 * 8 + 4);
        l0 = c0; l1 = c1;
    }
    size_t o = (size_t)idx * 8;
    *(float4*)&g_aug[o] = c0; *(float4*)&g_aug[o + 4] = c1;
    *(float4*)&g_aug[STREAM + o] = l0; *(float4*)&g_aug[STREAM + o + 4] = l1;
    uint4 hi, lo;
    split8(c0, c1, hi, lo);
    *(uint4*)&g_augH[o] = hi; *(uint4*)&g_augL[o] = lo;
    split8(l0, l1, hi, lo);
    *(uint4*)&g_augH[STREAM + o] = hi; *(uint4*)&g_augL[STREAM + o] = lo;
}

// ---------------- split weights once ----------------
__global__ void split_w_kernel(const float* __restrict__ W0, const float* __restrict__ W1,
                               const float* __restrict__ W2, const float* __restrict__ W3) {
    int idx = blockIdx.x * blockDim.x + threadIdx.x;   // 8-elem unit
    if (idx >= HID * HID / 8) return;
    int w = blockIdx.y;
    const float* src = (w == 0) ? W0 : (w == 1) ? W1 : (w == 2) ? W2 : W3;
    const float* p = src + (size_t)idx * 8;
    float4 v0 = *(const float4*)p, v1 = *(const float4*)(p + 4);
    uint4 hi, lo;
    split8(v0, v1, hi, lo);
    size_t o = (size_t)w * HID * HID + (size_t)idx * 8;
    *(uint4*)&g_WH[o] = hi;
    *(uint4*)&g_WL[o] = lo;
}

// ---------------- GEMM v2: pre-split bf16 operands, cp.async double buffer ----------------
__device__ __forceinline__ void gemm2_load_stage(
    uint32_t sb, int stg, int ch, int tid,
    const __nv_bfloat16* AH, const __nv_bfloat16* AL,
    const __nv_bfloat16* WH, const __nv_bfloat16* WL,
    int row0, int col0, int M) {
    uint32_t base = sb + stg * STG2;
#pragma unroll
    for (int i = 0; i < 4; i++) {
        int c = tid + i * 256;
        int row = c >> 3, col = c & 7;
        int gr = row0 + row;
        int sz = (gr < M) ? 16 : 0;
        size_t srcoff = (size_t)(sz ? gr : 0) * HID + ch * KC2 + col * 8;
        uint32_t d = base + row * A_STR2 + col * 16;
        cpasync16(d + SA_HI, AH + srcoff, sz);
        cpasync16(d + SA_LO, AL + srcoff, sz);
    }
#pragma unroll
    for (int i = 0; i < 4; i++) {
        int c = tid + i * 256;
        int row = c >> 4, col = c & 15;
        size_t srcoff = (size_t)(ch * KC2 + row) * HID + col0 + col * 8;
        uint32_t d = base + row * B_STR2 + col * 16;
        cpasync16(d + SB_HI, WH + srcoff, 16);
        cpasync16(d + SB_LO, WL + srcoff, 16);
    }
}

__global__ __launch_bounds__(256, 1) void gemm2_kernel(
    const __nv_bfloat16* __restrict__ AH, const __nv_bfloat16* __restrict__ AL,
    const __nv_bfloat16* __restrict__ WH, const __nv_bfloat16* __restrict__ WL,
    const float* __restrict__ bias, float* __restrict__ Cf,
    __nv_bfloat16* __restrict__ CH, __nv_bfloat16* __restrict__ CL, int M) {
    extern __shared__ char smc[];
    const uint32_t sb = smem_u32(smc);
    const int tid = threadIdx.x, lane = tid & 31, wid = tid >> 5;
    const int wm = wid >> 2, wn = wid & 3;
    const int row0 = blockIdx.y * TM, col0 = blockIdx.x * TN;

    float acc[4][4][4];
#pragma unroll
    for (int i = 0; i < 4; i++)
#pragma unroll
        for (int j = 0; j < 4; j++)
#pragma unroll
            for (int k = 0; k < 4; k++) acc[i][j][k] = 0.f;

    const uint32_t a_lane = (uint32_t)((lane & 15) * A_STR2 + (lane >> 4) * 16);
    const uint32_t b_lane = (uint32_t)(((((lane >> 3) & 1) * 8) + (lane & 7)) * B_STR2
                                       + (lane >> 4) * 16);

    gemm2_load_stage(sb, 0, 0, tid, AH, AL, WH, WL, row0, col0, M);
    cpcommit();

    for (int ch = 0; ch < NCH2; ch++) {
        if (ch + 1 < NCH2) {
            gemm2_load_stage(sb, (ch + 1) & 1, ch + 1, tid, AH, AL, WH, WL, row0, col0, M);
            cpcommit();
            cpwait<1>();
        } else {
            cpwait<0>();
        }
        __syncthreads();

        const uint32_t stg = sb + (ch & 1) * STG2;
#pragma unroll
        for (int ks = 0; ks < 4; ks++) {
            uint32_t ahi[4][4], alo[4][4], bhi[4][2], blo[4][2];
#pragma unroll
            for (int mt = 0; mt < 4; mt++) {
                uint32_t ao = stg + (uint32_t)((wm * 64 + mt * 16) * A_STR2 + ks * 32) + a_lane;
                ldmx4(ahi[mt], ao + SA_HI);
                ldmx4(alo[mt], ao + SA_LO);
            }
            {
                uint32_t bo = stg + (uint32_t)(ks * 16 * B_STR2 + wn * 64) + b_lane;
                uint32_t t[4];
                ldmx4t(t, bo + SB_HI);
                bhi[0][0]=t[0]; bhi[0][1]=t[1]; bhi[1][0]=t[2]; bhi[1][1]=t[3];
                ldmx4t(t, bo + SB_HI + 32);
                bhi[2][0]=t[0]; bhi[2][1]=t[1]; bhi[3][0]=t[2]; bhi[3][1]=t[3];
                ldmx4t(t, bo + SB_LO);
                blo[0][0]=t[0]; blo[0][1]=t[1]; blo[1][0]=t[2]; blo[1][1]=t[3];
                ldmx4t(t, bo + SB_LO + 32);
                blo[2][0]=t[0]; blo[2][1]=t[1]; blo[3][0]=t[2]; blo[3][1]=t[3];
            }
#pragma unroll
            for (int mt = 0; mt < 4; mt++)
#pragma unroll
                for (int nt = 0; nt < 4; nt++) {
                    mma16816(acc[mt][nt], ahi[mt], bhi[nt]);
                    mma16816(acc[mt][nt], ahi[mt], blo[nt]);
                    mma16816(acc[mt][nt], alo[mt], bhi[nt]);
                }
        }
        __syncthreads();
    }

    const int mb = row0 + wm * 64 + (lane >> 2);
    const int nb = col0 + wn * 32 + (lane & 3) * 2;
    if (CH) {
        // split-bf16 output
#pragma unroll
        for (int nt = 0; nt < 4; nt++) {
            const int n = nb + nt * 8;
            const float2 bv = *(const float2*)&bias[n];
#pragma unroll
            for (int mt = 0; mt < 4; mt++) {
                const int m = mb + mt * 16;
                if (m < M) {
                    float x = acc[mt][nt][0] + bv.x, y = acc[mt][nt][1] + bv.y;
                    __nv_bfloat16 hx, lx, hy, ly;
                    split2(x, hx, lx); split2(y, hy, ly);
                    *(uint32_t*)&CH[(size_t)m * HID + n] = pk_bf2(hx, hy);
                    *(uint32_t*)&CL[(size_t)m * HID + n] = pk_bf2(lx, ly);
                }
                if (m + 8 < M) {
                    float x = acc[mt][nt][2] + bv.x, y = acc[mt][nt][3] + bv.y;
                    __nv_bfloat16 hx, lx, hy, ly;
                    split2(x, hx, lx); split2(y, hy, ly);
                    *(uint32_t*)&CH[(size_t)(m + 8) * HID + n] = pk_bf2(hx, hy);
                    *(uint32_t*)&CL[(size_t)(m + 8) * HID + n] = pk_bf2(lx, ly);
                }
            }
        }
    } else {
#pragma unroll
        for (int nt = 0; nt < 4; nt++) {
            const int n = nb + nt * 8;
            const float2 bv = *(const float2*)&bias[n];
#pragma unroll
            for (int mt = 0; mt < 4; mt++) {
                const int m = mb + mt * 16;
                if (m < M)
                    *(float2*)&Cf[(size_t)m * HID + n] =
                        make_float2(acc[mt][nt][0] + bv.x, acc[mt][nt][1] + bv.y);
                if (m + 8 < M)
                    *(float2*)&Cf[(size_t)(m + 8) * HID + n] =
                        make_float2(acc[mt][nt][2] + bv.x, acc[mt][nt][3] + bv.y);
            }
        }
    }
}

// ---------------- attention v2: pre-split bf16, cp.async double buffer ----------------
__device__ __forceinline__ void attn2_load_arr(
    uint32_t dstbase, const __nv_bfloat16* src, size_t baseBH, int k0, int tid) {
#pragma unroll
    for (int i = 0; i < 2; i++) {
        int c = tid + i * 256;
        int row = c >> 3, col = c & 7;
        int gr = k0 + row;
        int sz = (gr < SA) ? 16 : 0;
        const __nv_bfloat16* s = src + baseBH + (size_t)(sz ? gr : 0) * HID + col * 8;
        cpasync16(dstbase + SWZ((uint32_t)(row * 128 + col * 16)), s, sz);
    }
}

__global__ __launch_bounds__(256) void attn2_kernel() {
    extern __shared__ char smc[];
    const uint32_t sb = smem_u32(smc);
    const int tid = threadIdx.x, lane = tid & 31, wid = tid >> 5;
    const int qt = blockIdx.x, bh = blockIdx.y, z = blockIdx.z;
    const int b = bh >> 4, h = bh & 15;

    const __nv_bfloat16* QH = g_QH + (size_t)z * STREAM;
    const __nv_bfloat16* QL = g_QL + (size_t)z * STREAM;
    const __nv_bfloat16* KH = g_KH + (size_t)(1 - z) * STREAM;
    const __nv_bfloat16* KL = g_KL + (size_t)(1 - z) * STREAM;
    const __nv_bfloat16* VH = g_VH + (size_t)(1 - z) * STREAM;
    const __nv_bfloat16* VL = g_VL + (size_t)(1 - z) * STREAM;
    __nv_bfloat16* OH = g_attH + (size_t)z * STREAM;
    __nv_bfloat16* OL = g_attL + (size_t)z * STREAM;
    const size_t baseBH = (size_t)b * SA * HID + h * HD;
    const int q0 = qt * 128;

    // ---- stage Q tile [128 x 64] (hi at 0, lo at 16384 in stage-0 area) ----
    for (int idx = tid; idx < 128 * 8; idx += 256) {
        int r = idx >> 3, c8 = (idx & 7) * 8;
        uint4 hi = make_uint4(0, 0, 0, 0), lo = hi;
        if (q0 + r < SA) {
            size_t g = baseBH + (size_t)(q0 + r) * HID + c8;
            hi = *(const uint4*)&QH[g];
            lo = *(const uint4*)&QL[g];
        }
        uint32_t off = SWZ((uint32_t)(r * 128 + c8 * 2));
        *(uint4*)(smc + off) = hi;
        *(uint4*)(smc + 16384 + off) = lo;
    }
    __syncthreads();

    uint32_t qh[4][4], ql[4][4];
#pragma unroll
    for (int ks = 0; ks < 4; ks++) {
        uint32_t off = SWZ((uint32_t)((wid * 16 + (lane & 15)) * 128 + ks * 32 + (lane >> 4) * 16));
        ldmx4(qh[ks], sb + off);
        ldmx4(ql[ks], sb + 16384 + off);
    }
    __syncthreads();   // done with Q staging area

    float o[8][4];
#pragma unroll
    for (int n = 0; n < 8; n++)
#pragma unroll
        for (int c = 0; c < 4; c++) o[n][c] = 0.f;
    float m0r = -INFINITY, m1r = -INFINITY, l0r = 0.f, l1r = 0.f;

    const int NT = (SA + 63) / 64;   // 33

    // prologue: stage 0
    attn2_load_arr(sb + AT2_KH, KH, baseBH, 0, tid);
    attn2_load_arr(sb + AT2_KL, KL, baseBH, 0, tid);
    attn2_load_arr(sb + AT2_VH, VH, baseBH, 0, tid);
    attn2_load_arr(sb + AT2_VL, VL, baseBH, 0, tid);
    cpcommit();

    for (int kt = 0; kt < NT; kt++) {
        const int k0 = kt * 64;
        if (kt + 1 < NT) {
            uint32_t nb = sb + ((kt + 1) & 1) * AT2_STG;
            attn2_load_arr(nb + AT2_KH, KH, baseBH, k0 + 64, tid);
            attn2_load_arr(nb + AT2_KL, KL, baseBH, k0 + 64, tid);
            attn2_load_arr(nb + AT2_VH, VH, baseBH, k0 + 64, tid);
            attn2_load_arr(nb + AT2_VL, VL, baseBH, k0 + 64, tid);
            cpcommit();
            cpwait<1>();
        } else {
            cpwait<0>();
        }
        __syncthreads();

        const uint32_t stg = sb + (kt & 1) * AT2_STG;

        // ---- S = Q @ K^T (3 split terms) ----
        float s[8][4];
#pragma unroll
        for (int n = 0; n < 8; n++)
#pragma unroll
            for (int c = 0; c < 4; c++) s[n][c] = 0.f;

#pragma unroll
        for (int kt2 = 0; kt2 < 4; kt2++) {
#pragma unroll
            for (int ks = 0; ks < 4; ks++) {
                uint32_t off = SWZ((uint32_t)((kt2 * 16 + (lane & 15)) * 128 + ks * 32 + (lane >> 4) * 16));
                uint32_t kb[4], kl[4];
                ldmx4(kb, stg + AT2_KH + off);
                ldmx4(kl, stg + AT2_KL + off);
                uint32_t blo_h[2] = {kb[0], kb[2]}, bhi_h[2] = {kb[1], kb[3]};
                uint32_t blo_l[2] = {kl[0], kl[2]}, bhi_l[2] = {kl[1], kl[3]};
                mma16816(s[2*kt2],     qh[ks], blo_h);
                mma16816(s[2*kt2],     qh[ks], blo_l);
                mma16816(s[2*kt2],     ql[ks], blo_h);
                mma16816(s[2*kt2 + 1], qh[ks], bhi_h);
                mma16816(s[2*kt2 + 1], qh[ks], bhi_l);
                mma16816(s[2*kt2 + 1], ql[ks], bhi_h);
            }
        }

        // ---- scale + mask ----
#pragma unroll
        for (int n = 0; n < 8; n++)
#pragma unroll
            for (int c = 0; c < 4; c++) s[n][c] *= 0.125f;
        if (k0 + 64 > SA) {
#pragma unroll
            for (int n = 0; n < 8; n++) {
                int ktc = k0 + (n >> 1) * 16 + (n & 1) * 8 + (lane & 3) * 2;
#pragma unroll
                for (int c = 0; c < 4; c++)
                    if (ktc + (c & 1) >= SA) s[n][c] = -1e30f;
            }
        }

        // ---- online softmax ----
        float mx0 = -INFINITY, mx1 = -INFINITY;
#pragma unroll
        for (int n = 0; n < 8; n++) {
            mx0 = fmaxf(mx0, fmaxf(s[n][0], s[n][1]));
            mx1 = fmaxf(mx1, fmaxf(s[n][2], s[n][3]));
        }
#pragma unroll
        for (int msk = 1; msk <= 2; msk <<= 1) {
            mx0 = fmaxf(mx0, __shfl_xor_sync(0xffffffffu, mx0, msk));
            mx1 = fmaxf(mx1, __shfl_xor_sync(0xffffffffu, mx1, msk));
        }
        float mn0 = fmaxf(m0r, mx0), mn1 = fmaxf(m1r, mx1);
        float c0 = __expf(m0r - mn0), c1 = __expf(m1r - mn1);
        m0r = mn0; m1r = mn1;
        float rs0 = 0.f, rs1 = 0.f;
#pragma unroll
        for (int n = 0; n < 8; n++) {
            s[n][0] = __expf(s[n][0] - mn0); rs0 += s[n][0];
            s[n][1] = __expf(s[n][1] - mn0); rs0 += s[n][1];
            s[n][2] = __expf(s[n][2] - mn1); rs1 += s[n][2];
            s[n][3] = __expf(s[n][3] - mn1); rs1 += s[n][3];
        }
#pragma unroll
        for (int msk = 1; msk <= 2; msk <<= 1) {
            rs0 += __shfl_xor_sync(0xffffffffu, rs0, msk);
            rs1 += __shfl_xor_sync(0xffffffffu, rs1, msk);
        }
        l0r = l0r * c0 + rs0;
        l1r = l1r * c1 + rs1;
#pragma unroll
        for (int n = 0; n < 8; n++) {
            o[n][0] *= c0; o[n][1] *= c0; o[n][2] *= c1; o[n][3] *= c1;
        }

        // ---- pack P (split) into a-frags ----
        uint32_t pah[4][4], pal[4][4];
#pragma unroll
        for (int ks = 0; ks < 4; ks++) {
            const int j0 = 2 * ks, j1 = 2 * ks + 1;
            __nv_bfloat16 hh[8], ll[8];
            split2(s[j0][0], hh[0], ll[0]); split2(s[j0][1], hh[1], ll[1]);
            split2(s[j0][2], hh[2], ll[2]); split2(s[j0][3], hh[3], ll[3]);
            split2(s[j1][0], hh[4], ll[4]); split2(s[j1][1], hh[5], ll[5]);
            split2(s[j1][2], hh[6], ll[6]); split2(s[j1][3], hh[7], ll[7]);
            pah[ks][0] = pk_bf2(hh[0], hh[1]); pah[ks][1] = pk_bf2(hh[2], hh[3]);
            pah[ks][2] = pk_bf2(hh[4], hh[5]); pah[ks][3] = pk_bf2(hh[6], hh[7]);
            pal[ks][0] = pk_bf2(ll[0], ll[1]); pal[ks][1] = pk_bf2(ll[2], ll[3]);
            pal[ks][2] = pk_bf2(ll[4], ll[5]); pal[ks][3] = pk_bf2(ll[6], ll[7]);
        }

        // ---- O += P @ V ----
        const uint32_t rp = ((lane >> 3) & 1) * 8 + (lane & 7);
#pragma unroll
        for (int dt = 0; dt < 4; dt++) {
#pragma unroll
            for (int ks = 0; ks < 4; ks++) {
                uint32_t off = SWZ((uint32_t)((ks * 16 + rp) * 128 + dt * 32 + (lane >> 4) * 16));
                uint32_t vb[4], vl[4];
                ldmx4t(vb, stg + AT2_VH + off);
                ldmx4t(vl, stg + AT2_VL + off);
                uint32_t b0h[2] = {vb[0], vb[1]}, b1h[2] = {vb[2], vb[3]};
                uint32_t b0l[2] = {vl[0], vl[1]}, b1l[2] = {vl[2], vl[3]};
                mma16816(o[2*dt],     pah[ks], b0h);
                mma16816(o[2*dt],     pah[ks], b0l);
                mma16816(o[2*dt],     pal[ks], b0h);
                mma16816(o[2*dt + 1], pah[ks], b1h);
                mma16816(o[2*dt + 1], pah[ks], b1l);
                mma16816(o[2*dt + 1], pal[ks], b1h);
            }
        }
        __syncthreads();
    }

    // ---- epilogue: normalize, split, store ----
    const int r0 = q0 + wid * 16 + (lane >> 2);
    const float inv0 = 1.0f / l0r, inv1 = 1.0f / l1r;
#pragma unroll
    for (int n = 0; n < 8; n++) {
        const int col = (n >> 1) * 16 + (n & 1) * 8 + (lane & 3) * 2;
        if (r0 < SA) {
            float x = o[n][0] * inv0, y = o[n][1] * inv0;
            __nv_bfloat16 hx, lx, hy, ly;
            split2(x, hx, lx); split2(y, hy, ly);
            size_t g = baseBH + (size_t)r0 * HID + col;
            *(uint32_t*)&OH[g] = pk_bf2(hx, hy);
            *(uint32_t*)&OL[g] = pk_bf2(lx, ly);
        }
        if (r0 + 8 < SA) {
            float x = o[n][2] * inv1, y = o[n][3] * inv1;
            __nv_bfloat16 hx, lx, hy, ly;
            split2(x, hx, lx); split2(y, hy, ly);
            size_t g = baseBH + (size_t)(r0 + 8) * HID + col;
            *(uint32_t*)&OH[g] = pk_bf2(hx, hy);
            *(uint32_t*)&OL[g] = pk_bf2(lx, ly);
        }
    }
}

// ---------------- residual + LayerNorm + slice -> output ----------------
__global__ __launch_bounds__(128) void ln_out_kernel(
    const float* __restrict__ gamma, const float* __restrict__ beta,
    float* __restrict__ out) {
    __shared__ float sbuf[4];
    const int row = blockIdx.x;
    const int c = row >> 12;
    const int r = row & 4095;
    const int b = r >> 11;
    const int s = r & 2047;
    const float* aug  = g_aug  + (size_t)c * STREAM;
    const float* proj = g_proj + (size_t)c * STREAM;
    const size_t base = ((size_t)b * SA + s) * HID;
    const int tid = threadIdx.x;

    float x[8];
    float4 a0 = *(const float4*)&aug[base + tid * 8];
    float4 a1 = *(const float4*)&aug[base + tid * 8 + 4];
    float4 p0 = *(const float4*)&proj[base + tid * 8];
    float4 p1 = *(const float4*)&proj[base + tid * 8 + 4];
    x[0] = a0.x + p0.x; x[1] = a0.y + p0.y; x[2] = a0.z + p0.z; x[3] = a0.w + p0.w;
    x[4] = a1.x + p1.x; x[5] = a1.y + p1.y; x[6] = a1.z + p1.z; x[7] = a1.w + p1.w;

    float sum = 0.f;
#pragma unroll
    for (int j = 0; j < 8; j++) sum += x[j];
#pragma unroll
    for (int m = 16; m >= 1; m >>= 1) sum += __shfl_xor_sync(0xffffffffu, sum, m);
    if ((tid & 31) == 0) sbuf[tid >> 5] = sum;
    __syncthreads();
    float mu = (sbuf[0] + sbuf[1] + sbuf[2] + sbuf[3]) * (1.0f / HID);
    __syncthreads();

    float vs = 0.f;
#pragma unroll
    for (int j = 0; j < 8; j++) { float d = x[j] - mu; vs += d * d; }
#pragma unroll
    for (int m = 16; m >= 1; m >>= 1) vs += __shfl_xor_sync(0xffffffffu, vs, m);
    if ((tid & 31) == 0) sbuf[tid >> 5] = vs;
    __syncthreads();
    float var = (sbuf[0] + sbuf[1] + sbuf[2] + sbuf[3]) * (1.0f / HID);
    float rstd = rsqrtf(var + 1e-5f);

    float* op = out + (size_t)c * (BB * SS * HID) + ((size_t)b * SS + s) * HID + tid * 8;
    float o[8];
#pragma unroll
    for (int j = 0; j < 8; j++) {
        int col = tid * 8 + j;
        o[j] = (x[j] - mu) * rstd * gamma[col] + beta[col];
    }
    *(float4*)(op)     = make_float4(o[0], o[1], o[2], o[3]);
    *(float4*)(op + 4) = make_float4(o[4], o[5], o[6], o[7]);
}

// ---------------- launch ----------------
extern "C" void kernel_launch(void* const* d_in, const int* in_sizes, int n_in,
                              void* d_out, int out_size) {
    const float* cnn      = (const float*)d_in[0];
    const float* llm      = (const float*)d_in[1];
    const float* Wq       = (const float*)d_in[2];
    const float* bq       = (const float*)d_in[3];
    const float* Wk       = (const float*)d_in[4];
    const float* bk       = (const float*)d_in[5];
    const float* Wv       = (const float*)d_in[6];
    const float* bv       = (const float*)d_in[7];
    const float* Wo       = (const float*)d_in[8];
    const float* bo       = (const float*)d_in[9];
    const float* energy   = (const float*)d_in[10];
    const float* mass     = (const float*)d_in[11];
    const float* momentum = (const float*)d_in[12];
    const float* gamma    = (const float*)d_in[13];
    const float* beta     = (const float*)d_in[14];
    float* out = (float*)d_out;

    __nv_bfloat16 *augH, *augL, *QH, *QL, *KH, *KL, *VH, *VL, *attH, *attL, *WH, *WL;
    float *projP;
    cudaGetSymbolAddress((void**)&augH, g_augH);
    cudaGetSymbolAddress((void**)&augL, g_augL);
    cudaGetSymbolAddress((void**)&QH, g_QH);
    cudaGetSymbolAddress((void**)&QL, g_QL);
    cudaGetSymbolAddress((void**)&KH, g_KH);
    cudaGetSymbolAddress((void**)&KL, g_KL);
    cudaGetSymbolAddress((void**)&VH, g_VH);
    cudaGetSymbolAddress((void**)&VL, g_VL);
    cudaGetSymbolAddress((void**)&attH, g_attH);
    cudaGetSymbolAddress((void**)&attL, g_attL);
    cudaGetSymbolAddress((void**)&WH, g_WH);
    cudaGetSymbolAddress((void**)&WL, g_WL);
    cudaGetSymbolAddress((void**)&projP, g_proj);

    const int tot8 = BB * SA * HID / 8;
    build_aug_kernel<<<(tot8 + 255) / 256, 256>>>(cnn, llm, energy, mass, momentum);

    dim3 wgrid(HID * HID / 8 / 256, 4);
    split_w_kernel<<<wgrid, 256>>>(Wq, Wk, Wv, Wo);

    cudaFuncSetAttribute(gemm2_kernel, cudaFuncAttributeMaxDynamicSharedMemorySize, GEMM2_SMEM);
    dim3 ggrid(HID / TN, (MTOT2 + TM - 1) / TM);   // (8, 65)
    const size_t WSZ = (size_t)HID * HID;
    gemm2_kernel<<<ggrid, 256, GEMM2_SMEM>>>(augH, augL, WH + 0*WSZ, WL + 0*WSZ, bq,
                                             nullptr, QH, QL, MTOT2);
    gemm2_kernel<<<ggrid, 256, GEMM2_SMEM>>>(augH, augL, WH + 1*WSZ, WL + 1*WSZ, bk,
                                             nullptr, KH, KL, MTOT2);
    gemm2_kernel<<<ggrid, 256, GEMM2_SMEM>>>(augH, augL, WH + 2*WSZ, WL + 2*WSZ, bv,
                                             nullptr, VH, VL, MTOT2);

    cudaFuncSetAttribute(attn2_kernel, cudaFuncAttributeMaxDynamicSharedMemorySize, ATTN2_SMEM);
    dim3 agrid((SA + 127) / 128, BB * NH, 2);      // (17, 32, 2)
    attn2_kernel<<<agrid, 256, ATTN2_SMEM>>>();

    gemm2_kernel<<<ggrid, 256, GEMM2_SMEM>>>(attH, attL, WH + 3*WSZ, WL + 3*WSZ, bo,
                                             projP, nullptr, nullptr, MTOT2);

    ln_out_kernel<<<2 * BB * SS, 128>>>(gamma, beta, out);
}

// round 6
// speedup vs baseline: 3.4792x; 1.0357x over previous
#include <cuda_runtime.h>
#include <cuda_bf16.h>
#include <math.h>
#include <cstdint>

#define BB 2
#define SS 2048
#define SA 2051            // S + 3 physics tokens
#define HID 1024
#define NH 16
#define HD 64
#define STREAM (BB*SA*HID) // elems per stream
#define MTOT2 (2*BB*SA)    // 8204 merged rows

#define SWZ(o) ((o) ^ (((o) >> 3) & 0x70))

// ---------------- GEMM v3 tiling (512 thr, 3-stage) ----------------
#define TM 128
#define TN 128
#define KC2 64
#define NCH2 (HID/KC2)     // 16
#define A_STR2 144         // 128B data + 16 pad
#define B_STR2 272         // 256B data + 16 pad
#define SA_HI 0
#define SA_LO (128*A_STR2)           // 18432
#define SB_HI (2*128*A_STR2)         // 36864
#define SB_LO (SB_HI + 64*B_STR2)    // 54272
#define STG2  (SB_LO + 64*B_STR2)    // 71680
#define GEMM3_SMEM (3*STG2)          // 215040

// ---------------- attention v3 smem ----------------
#define AT2_KH 0
#define AT2_KL 8192
#define AT2_VH 16384
#define AT2_VL 24576
#define AT2_STG 32768
#define ATTN2_SMEM (2*AT2_STG)       // 65536

// ---------------- device scratch ----------------
__device__ float g_aug[2*STREAM];            // fp32 residual
__device__ float g_proj[2*STREAM];           // out-proj fp32 result
__device__ __nv_bfloat16 g_augH[2*STREAM], g_augL[2*STREAM];
__device__ __nv_bfloat16 g_QH[2*STREAM], g_QL[2*STREAM];
__device__ __nv_bfloat16 g_KH[2*STREAM], g_KL[2*STREAM];
__device__ __nv_bfloat16 g_VH[2*STREAM], g_VL[2*STREAM];
__device__ __nv_bfloat16 g_attH[2*STREAM], g_attL[2*STREAM];
__device__ __nv_bfloat16 g_WH[4*HID*HID], g_WL[4*HID*HID];

// ---------------- helpers ----------------
__device__ __forceinline__ uint32_t smem_u32(const void* p) {
    uint32_t a;
    asm("{ .reg .u64 t; cvta.to.shared.u64 t, %1; cvt.u32.u64 %0, t; }" : "=r"(a) : "l"(p));
    return a;
}
__device__ __forceinline__ void mma16816(float* d, const uint32_t* a, const uint32_t* b) {
    asm volatile(
        "mma.sync.aligned.m16n8k16.row.col.f32.bf16.bf16.f32 "
        "{%0,%1,%2,%3}, {%4,%5,%6,%7}, {%8,%9}, {%0,%1,%2,%3};"
        : "+f"(d[0]), "+f"(d[1]), "+f"(d[2]), "+f"(d[3])
        : "r"(a[0]), "r"(a[1]), "r"(a[2]), "r"(a[3]), "r"(b[0]), "r"(b[1]));
}
__device__ __forceinline__ void ldmx4(uint32_t* r, uint32_t addr) {
    asm volatile("ldmatrix.sync.aligned.m8n8.x4.shared.b16 {%0,%1,%2,%3}, [%4];"
                 : "=r"(r[0]), "=r"(r[1]), "=r"(r[2]), "=r"(r[3]) : "r"(addr));
}
__device__ __forceinline__ void ldmx4t(uint32_t* r, uint32_t addr) {
    asm volatile("ldmatrix.sync.aligned.m8n8.x4.trans.shared.b16 {%0,%1,%2,%3}, [%4];"
                 : "=r"(r[0]), "=r"(r[1]), "=r"(r[2]), "=r"(r[3]) : "r"(addr));
}
__device__ __forceinline__ void cpasync16(uint32_t dst, const void* src, int sz) {
    asm volatile("cp.async.cg.shared.global [%0], [%1], 16, %2;"
                 :: "r"(dst), "l"(src), "r"(sz));
}
__device__ __forceinline__ void cpcommit() { asm volatile("cp.async.commit_group;" ::: "memory"); }
template<int N> __device__ __forceinline__ void cpwait() {
    asm volatile("cp.async.wait_group %0;" :: "n"(N) : "memory");
}
__device__ __forceinline__ uint32_t pk_bf2(__nv_bfloat16 a, __nv_bfloat16 b) {
    __nv_bfloat162 t(a, b);
    return *reinterpret_cast<uint32_t*>(&t);
}
__device__ __forceinline__ void split2(float f, __nv_bfloat16& h, __nv_bfloat16& l) {
    h = __float2bfloat16(f);
    l = __float2bfloat16(f - __bfloat162float(h));
}
__device__ __forceinline__ void split8(float4 v0, float4 v1, uint4& hi, uint4& lo) {
    __nv_bfloat16 h[8], l[8];
    float f[8] = {v0.x, v0.y, v0.z, v0.w, v1.x, v1.y, v1.z, v1.w};
#pragma unroll
    for (int j = 0; j < 8; j++) split2(f[j], h[j], l[j]);
    hi = make_uint4(pk_bf2(h[0], h[1]), pk_bf2(h[2], h[3]), pk_bf2(h[4], h[5]), pk_bf2(h[6], h[7]));
    lo = make_uint4(pk_bf2(l[0], l[1]), pk_bf2(l[2], l[3]), pk_bf2(l[4], l[5]), pk_bf2(l[6], l[7]));
}

// ---------------- build augmented sequences (fp32 + split bf16) ----------------
__global__ void build_aug_kernel(const float* __restrict__ cnn,
                                 const float* __restrict__ llm,
                                 const float* __restrict__ energy,
                                 const float* __restrict__ mass,
                                 const float* __restrict__ momentum) {
    int idx = blockIdx.x * blockDim.x + threadIdx.x;   // 8-float unit
    const int total = BB * SA * HID / 8;
    if (idx >= total) return;
    int h8  = idx % (HID / 8);
    int row = idx / (HID / 8);
    int s   = row % SA;
    int b   = row / SA;
    float4 c0, c1, l0, l1;
    if (s < SS) {
        const float* cp = cnn + ((size_t)(b * SS + s) * HID) + h8 * 8;
        const float* lp = llm + ((size_t)(b * SS + s) * HID) + h8 * 8;
        c0 = *(const float4*)cp; c1 = *(const float4*)(cp + 4);
        l0 = *(const float4*)lp; l1 = *(const float4*)(lp + 4);
    } else {
        const float* e = (s == SS) ? energy : ((s == SS + 1) ? mass : momentum);
        c0 = *(const float4*)(e + h8 * 8); c1 = *(const float4*)(e + h8 * 8 + 4);
        l0 = c0; l1 = c1;
    }
    size_t o = (size_t)idx * 8;
    *(float4*)&g_aug[o] = c0; *(float4*)&g_aug[o + 4] = c1;
    *(float4*)&g_aug[STREAM + o] = l0; *(float4*)&g_aug[STREAM + o + 4] = l1;
    uint4 hi, lo;
    split8(c0, c1, hi, lo);
    *(uint4*)&g_augH[o] = hi; *(uint4*)&g_augL[o] = lo;
    split8(l0, l1, hi, lo);
    *(uint4*)&g_augH[STREAM + o] = hi; *(uint4*)&g_augL[STREAM + o] = lo;
}

// ---------------- split weights once ----------------
__global__ void split_w_kernel(const float* __restrict__ W0, const float* __restrict__ W1,
                               const float* __restrict__ W2, const float* __restrict__ W3) {
    int idx = blockIdx.x * blockDim.x + threadIdx.x;   // 8-elem unit
    if (idx >= HID * HID / 8) return;
    int w = blockIdx.y;
    const float* src = (w == 0) ? W0 : (w == 1) ? W1 : (w == 2) ? W2 : W3;
    const float* p = src + (size_t)idx * 8;
    float4 v0 = *(const float4*)p, v1 = *(const float4*)(p + 4);
    uint4 hi, lo;
    split8(v0, v1, hi, lo);
    size_t o = (size_t)w * HID * HID + (size_t)idx * 8;
    *(uint4*)&g_WH[o] = hi;
    *(uint4*)&g_WL[o] = lo;
}

// ---------------- GEMM v3: 512 threads, 3-stage cp.async pipeline ----------------
__device__ __forceinline__ void gemm3_load_stage(
    uint32_t sb, int stg, int ch, int tid,
    const __nv_bfloat16* AH, const __nv_bfloat16* AL,
    const __nv_bfloat16* WH, const __nv_bfloat16* WL,
    int row0, int col0, int M) {
    uint32_t base = sb + stg * STG2;
#pragma unroll
    for (int i = 0; i < 2; i++) {
        int c = tid + i * 512;
        int row = c >> 3, col = c & 7;
        int gr = row0 + row;
        int sz = (gr < M) ? 16 : 0;
        size_t srcoff = (size_t)(sz ? gr : 0) * HID + ch * KC2 + col * 8;
        uint32_t d = base + row * A_STR2 + col * 16;
        cpasync16(d + SA_HI, AH + srcoff, sz);
        cpasync16(d + SA_LO, AL + srcoff, sz);
    }
#pragma unroll
    for (int i = 0; i < 2; i++) {
        int c = tid + i * 512;
        int row = c >> 4, col = c & 15;
        size_t srcoff = (size_t)(ch * KC2 + row) * HID + col0 + col * 8;
        uint32_t d = base + row * B_STR2 + col * 16;
        cpasync16(d + SB_HI, WH + srcoff, 16);
        cpasync16(d + SB_LO, WL + srcoff, 16);
    }
}

__global__ __launch_bounds__(512, 1) void gemm3_kernel(
    const __nv_bfloat16* __restrict__ AH, const __nv_bfloat16* __restrict__ AL,
    const __nv_bfloat16* __restrict__ WH, const __nv_bfloat16* __restrict__ WL,
    const float* __restrict__ bias, float* __restrict__ Cf,
    __nv_bfloat16* __restrict__ CH, __nv_bfloat16* __restrict__ CL, int M) {
    extern __shared__ char smc[];
    const uint32_t sb = smem_u32(smc);
    const int tid = threadIdx.x, lane = tid & 31, wid = tid >> 5;
    const int wm = wid >> 2, wn = wid & 3;   // 4m x 4n warps, 32x32 tiles
    const int row0 = blockIdx.y * TM, col0 = blockIdx.x * TN;

    float acc[2][4][4];
#pragma unroll
    for (int i = 0; i < 2; i++)
#pragma unroll
        for (int j = 0; j < 4; j++)
#pragma unroll
            for (int k = 0; k < 4; k++) acc[i][j][k] = 0.f;

    const uint32_t a_lane = (uint32_t)((lane & 15) * A_STR2 + (lane >> 4) * 16);
    const uint32_t b_lane = (uint32_t)(((((lane >> 3) & 1) * 8) + (lane & 7)) * B_STR2
                                       + (lane >> 4) * 16);

    gemm3_load_stage(sb, 0, 0, tid, AH, AL, WH, WL, row0, col0, M);
    cpcommit();
    gemm3_load_stage(sb, 1, 1, tid, AH, AL, WH, WL, row0, col0, M);
    cpcommit();

    int slot = 0;
    for (int ch = 0; ch < NCH2; ch++) {
        if (ch + 2 < NCH2) {
            int ns = slot + 2; if (ns >= 3) ns -= 3;
            gemm3_load_stage(sb, ns, ch + 2, tid, AH, AL, WH, WL, row0, col0, M);
            cpcommit();
            cpwait<2>();
        } else if (ch + 1 < NCH2) {
            cpwait<1>();
        } else {
            cpwait<0>();
        }
        __syncthreads();

        const uint32_t stg = sb + slot * STG2;
#pragma unroll
        for (int ks = 0; ks < 4; ks++) {
            uint32_t ahi[2][4], alo[2][4], bhi[4][2], blo[4][2];
#pragma unroll
            for (int mt = 0; mt < 2; mt++) {
                uint32_t ao = stg + (uint32_t)((wm * 32 + mt * 16) * A_STR2 + ks * 32) + a_lane;
                ldmx4(ahi[mt], ao + SA_HI);
                ldmx4(alo[mt], ao + SA_LO);
            }
            {
                uint32_t bo = stg + (uint32_t)(ks * 16 * B_STR2 + wn * 64) + b_lane;
                uint32_t t[4];
                ldmx4t(t, bo + SB_HI);
                bhi[0][0]=t[0]; bhi[0][1]=t[1]; bhi[1][0]=t[2]; bhi[1][1]=t[3];
                ldmx4t(t, bo + SB_HI + 32);
                bhi[2][0]=t[0]; bhi[2][1]=t[1]; bhi[3][0]=t[2]; bhi[3][1]=t[3];
                ldmx4t(t, bo + SB_LO);
                blo[0][0]=t[0]; blo[0][1]=t[1]; blo[1][0]=t[2]; blo[1][1]=t[3];
                ldmx4t(t, bo + SB_LO + 32);
                blo[2][0]=t[0]; blo[2][1]=t[1]; blo[3][0]=t[2]; blo[3][1]=t[3];
            }
#pragma unroll
            for (int mt = 0; mt < 2; mt++)
#pragma unroll
                for (int nt = 0; nt < 4; nt++) {
                    mma16816(acc[mt][nt], ahi[mt], bhi[nt]);
                    mma16816(acc[mt][nt], ahi[mt], blo[nt]);
                    mma16816(acc[mt][nt], alo[mt], bhi[nt]);
                }
        }
        __syncthreads();
        if (++slot == 3) slot = 0;
    }

    const int mb = row0 + wm * 32 + (lane >> 2);
    const int nb = col0 + wn * 32 + (lane & 3) * 2;
    if (CH) {
#pragma unroll
        for (int nt = 0; nt < 4; nt++) {
            const int n = nb + nt * 8;
            const float2 bv = *(const float2*)&bias[n];
#pragma unroll
            for (int mt = 0; mt < 2; mt++) {
                const int m = mb + mt * 16;
                if (m < M) {
                    float x = acc[mt][nt][0] + bv.x, y = acc[mt][nt][1] + bv.y;
                    __nv_bfloat16 hx, lx, hy, ly;
                    split2(x, hx, lx); split2(y, hy, ly);
                    *(uint32_t*)&CH[(size_t)m * HID + n] = pk_bf2(hx, hy);
                    *(uint32_t*)&CL[(size_t)m * HID + n] = pk_bf2(lx, ly);
                }
                if (m + 8 < M) {
                    float x = acc[mt][nt][2] + bv.x, y = acc[mt][nt][3] + bv.y;
                    __nv_bfloat16 hx, lx, hy, ly;
                    split2(x, hx, lx); split2(y, hy, ly);
                    *(uint32_t*)&CH[(size_t)(m + 8) * HID + n] = pk_bf2(hx, hy);
                    *(uint32_t*)&CL[(size_t)(m + 8) * HID + n] = pk_bf2(lx, ly);
                }
            }
        }
    } else {
#pragma unroll
        for (int nt = 0; nt < 4; nt++) {
            const int n = nb + nt * 8;
            const float2 bv = *(const float2*)&bias[n];
#pragma unroll
            for (int mt = 0; mt < 2; mt++) {
                const int m = mb + mt * 16;
                if (m < M)
                    *(float2*)&Cf[(size_t)m * HID + n] =
                        make_float2(acc[mt][nt][0] + bv.x, acc[mt][nt][1] + bv.y);
                if (m + 8 < M)
                    *(float2*)&Cf[(size_t)(m + 8) * HID + n] =
                        make_float2(acc[mt][nt][2] + bv.x, acc[mt][nt][3] + bv.y);
            }
        }
    }
}

// ---------------- attention v3: 512 threads, Br=256 ----------------
__device__ __forceinline__ void attn3_load_arr(
    uint32_t dstbase, const __nv_bfloat16* src, size_t baseBH, int k0, int tid) {
    int row = tid >> 3, col = tid & 7;
    int gr = k0 + row;
    int sz = (gr < SA) ? 16 : 0;
    const __nv_bfloat16* s = src + baseBH + (size_t)(sz ? gr : 0) * HID + col * 8;
    cpasync16(dstbase + SWZ((uint32_t)(row * 128 + col * 16)), s, sz);
}

__global__ __launch_bounds__(512, 1) void attn3_kernel() {
    extern __shared__ char smc[];
    const uint32_t sb = smem_u32(smc);
    const int tid = threadIdx.x, lane = tid & 31, wid = tid >> 5;
    const int qt = blockIdx.x, bh = blockIdx.y, z = blockIdx.z;
    const int b = bh >> 4, h = bh & 15;

    const __nv_bfloat16* QH = g_QH + (size_t)z * STREAM;
    const __nv_bfloat16* QL = g_QL + (size_t)z * STREAM;
    const __nv_bfloat16* KH = g_KH + (size_t)(1 - z) * STREAM;
    const __nv_bfloat16* KL = g_KL + (size_t)(1 - z) * STREAM;
    const __nv_bfloat16* VH = g_VH + (size_t)(1 - z) * STREAM;
    const __nv_bfloat16* VL = g_VL + (size_t)(1 - z) * STREAM;
    __nv_bfloat16* OH = g_attH + (size_t)z * STREAM;
    __nv_bfloat16* OL = g_attL + (size_t)z * STREAM;
    const size_t baseBH = (size_t)b * SA * HID + h * HD;
    const int q0 = qt * 256;

    // ---- stage Q in two 128-row halves; each half of the warps grabs its frags ----
    uint32_t qh[4][4], ql[4][4];
#pragma unroll 1
    for (int h2 = 0; h2 < 2; h2++) {
        for (int idx = tid; idx < 128 * 8; idx += 512) {
            int r = idx >> 3, c8 = (idx & 7) * 8;
            uint4 hi = make_uint4(0, 0, 0, 0), lo = hi;
            int gr = q0 + h2 * 128 + r;
            if (gr < SA) {
                size_t g = baseBH + (size_t)gr * HID + c8;
                hi = *(const uint4*)&QH[g];
                lo = *(const uint4*)&QL[g];
            }
            uint32_t off = SWZ((uint32_t)(r * 128 + c8 * 2));
            *(uint4*)(smc + off) = hi;
            *(uint4*)(smc + 16384 + off) = lo;
        }
        __syncthreads();
        if ((wid >> 3) == h2) {
#pragma unroll
            for (int ks = 0; ks < 4; ks++) {
                uint32_t off = SWZ((uint32_t)(((wid & 7) * 16 + (lane & 15)) * 128
                                              + ks * 32 + (lane >> 4) * 16));
                ldmx4(qh[ks], sb + off);
                ldmx4(ql[ks], sb + 16384 + off);
            }
        }
        __syncthreads();
    }

    float o[8][4];
#pragma unroll
    for (int n = 0; n < 8; n++)
#pragma unroll
        for (int c = 0; c < 4; c++) o[n][c] = 0.f;
    float m0r = -INFINITY, m1r = -INFINITY, l0r = 0.f, l1r = 0.f;

    const int NT = (SA + 63) / 64;   // 33

    attn3_load_arr(sb + AT2_KH, KH, baseBH, 0, tid);
    attn3_load_arr(sb + AT2_KL, KL, baseBH, 0, tid);
    attn3_load_arr(sb + AT2_VH, VH, baseBH, 0, tid);
    attn3_load_arr(sb + AT2_VL, VL, baseBH, 0, tid);
    cpcommit();

    for (int kt = 0; kt < NT; kt++) {
        const int k0 = kt * 64;
        if (kt + 1 < NT) {
            uint32_t nb = sb + ((kt + 1) & 1) * AT2_STG;
            attn3_load_arr(nb + AT2_KH, KH, baseBH, k0 + 64, tid);
            attn3_load_arr(nb + AT2_KL, KL, baseBH, k0 + 64, tid);
            attn3_load_arr(nb + AT2_VH, VH, baseBH, k0 + 64, tid);
            attn3_load_arr(nb + AT2_VL, VL, baseBH, k0 + 64, tid);
            cpcommit();
            cpwait<1>();
        } else {
            cpwait<0>();
        }
        __syncthreads();

        const uint32_t stg = sb + (kt & 1) * AT2_STG;

        // ---- S = Q @ K^T (3 split terms) ----
        float s[8][4];
#pragma unroll
        for (int n = 0; n < 8; n++)
#pragma unroll
            for (int c = 0; c < 4; c++) s[n][c] = 0.f;

#pragma unroll
        for (int kt2 = 0; kt2 < 4; kt2++) {
#pragma unroll
            for (int ks = 0; ks < 4; ks++) {
                uint32_t off = SWZ((uint32_t)((kt2 * 16 + (lane & 15)) * 128 + ks * 32 + (lane >> 4) * 16));
                uint32_t kb[4], kl[4];
                ldmx4(kb, stg + AT2_KH + off);
                ldmx4(kl, stg + AT2_KL + off);
                uint32_t blo_h[2] = {kb[0], kb[2]}, bhi_h[2] = {kb[1], kb[3]};
                uint32_t blo_l[2] = {kl[0], kl[2]}, bhi_l[2] = {kl[1], kl[3]};
                mma16816(s[2*kt2],     qh[ks], blo_h);
                mma16816(s[2*kt2],     qh[ks], blo_l);
                mma16816(s[2*kt2],     ql[ks], blo_h);
                mma16816(s[2*kt2 + 1], qh[ks], bhi_h);
                mma16816(s[2*kt2 + 1], qh[ks], bhi_l);
                mma16816(s[2*kt2 + 1], ql[ks], bhi_h);
            }
        }

        // ---- scale + mask ----
#pragma unroll
        for (int n = 0; n < 8; n++)
#pragma unroll
            for (int c = 0; c < 4; c++) s[n][c] *= 0.125f;
        if (k0 + 64 > SA) {
#pragma unroll
            for (int n = 0; n < 8; n++) {
                int ktc = k0 + (n >> 1) * 16 + (n & 1) * 8 + (lane & 3) * 2;
#pragma unroll
                for (int c = 0; c < 4; c++)
                    if (ktc + (c & 1) >= SA) s[n][c] = -1e30f;
            }
        }

        // ---- online softmax ----
        float mx0 = -INFINITY, mx1 = -INFINITY;
#pragma unroll
        for (int n = 0; n < 8; n++) {
            mx0 = fmaxf(mx0, fmaxf(s[n][0], s[n][1]));
            mx1 = fmaxf(mx1, fmaxf(s[n][2], s[n][3]));
        }
#pragma unroll
        for (int msk = 1; msk <= 2; msk <<= 1) {
            mx0 = fmaxf(mx0, __shfl_xor_sync(0xffffffffu, mx0, msk));
            mx1 = fmaxf(mx1, __shfl_xor_sync(0xffffffffu, mx1, msk));
        }
        float mn0 = fmaxf(m0r, mx0), mn1 = fmaxf(m1r, mx1);
        float c0 = __expf(m0r - mn0), c1 = __expf(m1r - mn1);
        m0r = mn0; m1r = mn1;
        float rs0 = 0.f, rs1 = 0.f;
#pragma unroll
        for (int n = 0; n < 8; n++) {
            s[n][0] = __expf(s[n][0] - mn0); rs0 += s[n][0];
            s[n][1] = __expf(s[n][1] - mn0); rs0 += s[n][1];
            s[n][2] = __expf(s[n][2] - mn1); rs1 += s[n][2];
            s[n][3] = __expf(s[n][3] - mn1); rs1 += s[n][3];
        }
#pragma unroll
        for (int msk = 1; msk <= 2; msk <<= 1) {
            rs0 += __shfl_xor_sync(0xffffffffu, rs0, msk);
            rs1 += __shfl_xor_sync(0xffffffffu, rs1, msk);
        }
        l0r = l0r * c0 + rs0;
        l1r = l1r * c1 + rs1;
#pragma unroll
        for (int n = 0; n < 8; n++) {
            o[n][0] *= c0; o[n][1] *= c0; o[n][2] *= c1; o[n][3] *= c1;
        }

        // ---- pack P (split) into a-frags ----
        uint32_t pah[4][4], pal[4][4];
#pragma unroll
        for (int ks = 0; ks < 4; ks++) {
            const int j0 = 2 * ks, j1 = 2 * ks + 1;
            __nv_bfloat16 hh[8], ll[8];
            split2(s[j0][0], hh[0], ll[0]); split2(s[j0][1], hh[1], ll[1]);
            split2(s[j0][2], hh[2], ll[2]); split2(s[j0][3], hh[3], ll[3]);
            split2(s[j1][0], hh[4], ll[4]); split2(s[j1][1], hh[5], ll[5]);
            split2(s[j1][2], hh[6], ll[6]); split2(s[j1][3], hh[7], ll[7]);
            pah[ks][0] = pk_bf2(hh[0], hh[1]); pah[ks][1] = pk_bf2(hh[2], hh[3]);
            pah[ks][2] = pk_bf2(hh[4], hh[5]); pah[ks][3] = pk_bf2(hh[6], hh[7]);
            pal[ks][0] = pk_bf2(ll[0], ll[1]); pal[ks][1] = pk_bf2(ll[2], ll[3]);
            pal[ks][2] = pk_bf2(ll[4], ll[5]); pal[ks][3] = pk_bf2(ll[6], ll[7]);
        }

        // ---- O += P @ V ----
        const uint32_t rp = ((lane >> 3) & 1) * 8 + (lane & 7);
#pragma unroll
        for (int dt = 0; dt < 4; dt++) {
#pragma unroll
            for (int ks = 0; ks < 4; ks++) {
                uint32_t off = SWZ((uint32_t)((ks * 16 + rp) * 128 + dt * 32 + (lane >> 4) * 16));
                uint32_t vb[4], vl[4];
                ldmx4t(vb, stg + AT2_VH + off);
                ldmx4t(vl, stg + AT2_VL + off);
                uint32_t b0h[2] = {vb[0], vb[1]}, b1h[2] = {vb[2], vb[3]};
                uint32_t b0l[2] = {vl[0], vl[1]}, b1l[2] = {vl[2], vl[3]};
                mma16816(o[2*dt],     pah[ks], b0h);
                mma16816(o[2*dt],     pah[ks], b0l);
                mma16816(o[2*dt],     pal[ks], b0h);
                mma16816(o[2*dt + 1], pah[ks], b1h);
                mma16816(o[2*dt + 1], pah[ks], b1l);
                mma16816(o[2*dt + 1], pal[ks], b1h);
            }
        }
        __syncthreads();
    }

    // ---- epilogue: normalize, split, store ----
    const int r0 = q0 + wid * 16 + (lane >> 2);
    const float inv0 = 1.0f / l0r, inv1 = 1.0f / l1r;
#pragma unroll
    for (int n = 0; n < 8; n++) {
        const int col = (n >> 1) * 16 + (n & 1) * 8 + (lane & 3) * 2;
        if (r0 < SA) {
            float x = o[n][0] * inv0, y = o[n][1] * inv0;
            __nv_bfloat16 hx, lx, hy, ly;
            split2(x, hx, lx); split2(y, hy, ly);
            size_t g = baseBH + (size_t)r0 * HID + col;
            *(uint32_t*)&OH[g] = pk_bf2(hx, hy);
            *(uint32_t*)&OL[g] = pk_bf2(lx, ly);
        }
        if (r0 + 8 < SA) {
            float x = o[n][2] * inv1, y = o[n][3] * inv1;
            __nv_bfloat16 hx, lx, hy, ly;
            split2(x, hx, lx); split2(y, hy, ly);
            size_t g = baseBH + (size_t)(r0 + 8) * HID + col;
            *(uint32_t*)&OH[g] = pk_bf2(hx, hy);
            *(uint32_t*)&OL[g] = pk_bf2(lx, ly);
        }
    }
}

// ---------------- residual + LayerNorm + slice -> output ----------------
__global__ __launch_bounds__(128) void ln_out_kernel(
    const float* __restrict__ gamma, const float* __restrict__ beta,
    float* __restrict__ out) {
    __shared__ float sbuf[4];
    const int row = blockIdx.x;
    const int c = row >> 12;
    const int r = row & 4095;
    const int b = r >> 11;
    const int s = r & 2047;
    const float* aug  = g_aug  + (size_t)c * STREAM;
    const float* proj = g_proj + (size_t)c * STREAM;
    const size_t base = ((size_t)b * SA + s) * HID;
    const int tid = threadIdx.x;

    float x[8];
    float4 a0 = *(const float4*)&aug[base + tid * 8];
    float4 a1 = *(const float4*)&aug[base + tid * 8 + 4];
    float4 p0 = *(const float4*)&proj[base + tid * 8];
    float4 p1 = *(const float4*)&proj[base + tid * 8 + 4];
    x[0] = a0.x + p0.x; x[1] = a0.y + p0.y; x[2] = a0.z + p0.z; x[3] = a0.w + p0.w;
    x[4] = a1.x + p1.x; x[5] = a1.y + p1.y; x[6] = a1.z + p1.z; x[7] = a1.w + p1.w;

    float sum = 0.f;
#pragma unroll
    for (int j = 0; j < 8; j++) sum += x[j];
#pragma unroll
    for (int m = 16; m >= 1; m >>= 1) sum += __shfl_xor_sync(0xffffffffu, sum, m);
    if ((tid & 31) == 0) sbuf[tid >> 5] = sum;
    __syncthreads();
    float mu = (sbuf[0] + sbuf[1] + sbuf[2] + sbuf[3]) * (1.0f / HID);
    __syncthreads();

    float vs = 0.f;
#pragma unroll
    for (int j = 0; j < 8; j++) { float d = x[j] - mu; vs += d * d; }
#pragma unroll
    for (int m = 16; m >= 1; m >>= 1) vs += __shfl_xor_sync(0xffffffffu, vs, m);
    if ((tid & 31) == 0) sbuf[tid >> 5] = vs;
    __syncthreads();
    float var = (sbuf[0] + sbuf[1] + sbuf[2] + sbuf[3]) * (1.0f / HID);
    float rstd = rsqrtf(var + 1e-5f);

    float* op = out + (size_t)c * (BB * SS * HID) + ((size_t)b * SS + s) * HID + tid * 8;
    float o[8];
#pragma unroll
    for (int j = 0; j < 8; j++) {
        int col = tid * 8 + j;
        o[j] = (x[j] - mu) * rstd * gamma[col] + beta[col];
    }
    *(float4*)(op)     = make_float4(o[0], o[1], o[2], o[3]);
    *(float4*)(op + 4) = make_float4(o[4], o[5], o[6], o[7]);
}

// ---------------- launch ----------------
extern "C" void kernel_launch(void* const* d_in, const int* in_sizes, int n_in,
                              void* d_out, int out_size) {
    const float* cnn      = (const float*)d_in[0];
    const float* llm      = (const float*)d_in[1];
    const float* Wq       = (const float*)d_in[2];
    const float* bq       = (const float*)d_in[3];
    const float* Wk       = (const float*)d_in[4];
    const float* bk       = (const float*)d_in[5];
    const float* Wv       = (const float*)d_in[6];
    const float* bv       = (const float*)d_in[7];
    const float* Wo       = (const float*)d_in[8];
    const float* bo       = (const float*)d_in[9];
    const float* energy   = (const float*)d_in[10];
    const float* mass     = (const float*)d_in[11];
    const float* momentum = (const float*)d_in[12];
    const float* gamma    = (const float*)d_in[13];
    const float* beta     = (const float*)d_in[14];
    float* out = (float*)d_out;

    __nv_bfloat16 *augH, *augL, *QH, *QL, *KH, *KL, *VH, *VL, *attH, *attL, *WH, *WL;
    float *projP;
    cudaGetSymbolAddress((void**)&augH, g_augH);
    cudaGetSymbolAddress((void**)&augL, g_augL);
    cudaGetSymbolAddress((void**)&QH, g_QH);
    cudaGetSymbolAddress((void**)&QL, g_QL);
    cudaGetSymbolAddress((void**)&KH, g_KH);
    cudaGetSymbolAddress((void**)&KL, g_KL);
    cudaGetSymbolAddress((void**)&VH, g_VH);
    cudaGetSymbolAddress((void**)&VL, g_VL);
    cudaGetSymbolAddress((void**)&attH, g_attH);
    cudaGetSymbolAddress((void**)&attL, g_attL);
    cudaGetSymbolAddress((void**)&WH, g_WH);
    cudaGetSymbolAddress((void**)&WL, g_WL);
    cudaGetSymbolAddress((void**)&projP, g_proj);

    const int tot8 = BB * SA * HID / 8;
    build_aug_kernel<<<(tot8 + 255) / 256, 256>>>(cnn, llm, energy, mass, momentum);

    dim3 wgrid(HID * HID / 8 / 256, 4);
    split_w_kernel<<<wgrid, 256>>>(Wq, Wk, Wv, Wo);

    cudaFuncSetAttribute(gemm3_kernel, cudaFuncAttributeMaxDynamicSharedMemorySize, GEMM3_SMEM);
    dim3 ggrid(HID / TN, (MTOT2 + TM - 1) / TM);   // (8, 65)
    const size_t WSZ = (size_t)HID * HID;
    gemm3_kernel<<<ggrid, 512, GEMM3_SMEM>>>(augH, augL, WH + 0*WSZ, WL + 0*WSZ, bq,
                                             nullptr, QH, QL, MTOT2);
    gemm3_kernel<<<ggrid, 512, GEMM3_SMEM>>>(augH, augL, WH + 1*WSZ, WL + 1*WSZ, bk,
                                             nullptr, KH, KL, MTOT2);
    gemm3_kernel<<<ggrid, 512, GEMM3_SMEM>>>(augH, augL, WH + 2*WSZ, WL + 2*WSZ, bv,
                                             nullptr, VH, VL, MTOT2);

    cudaFuncSetAttribute(attn3_kernel, cudaFuncAttributeMaxDynamicSharedMemorySize, ATTN2_SMEM);
    dim3 agrid((SA + 255) / 256, BB * NH, 2);      // (9, 32, 2)
    attn3_kernel<<<agrid, 512, ATTN2_SMEM>>>();

    gemm3_kernel<<<ggrid, 512, GEMM3_SMEM>>>(attH, attL, WH + 3*WSZ, WL + 3*WSZ, bo,
                                             projP, nullptr, nullptr, MTOT2);

    ln_out_kernel<<<2 * BB * SS, 128>>>(gamma, beta, out);
}

// round 7
// speedup vs baseline: 3.7526x; 1.0786x over previous
#include <cuda_runtime.h>
#include <cuda_bf16.h>
#include <math.h>
#include <cstdint>

#define BB 2
#define SS 2048
#define SA 2051            // S + 3 physics tokens
#define HID 1024
#define NH 16
#define HD 64
#define STREAM (BB*SA*HID) // elems per stream
#define MTOT2 (2*BB*SA)    // 8204 merged rows
#define WSZ (HID*HID)

#define SWZ(o) ((o) ^ (((o) >> 3) & 0x70))

// ---------------- GEMM v4 tiling (256 thr, warp 64x64, CTA 128x256, 2-stage) ----
#define TM 128
#define TN3 256
#define KC2 64
#define NCH2 (HID/KC2)     // 16
#define A_STR2 144         // 128B data + 16 pad
#define B_STR3 528         // 512B data + 16 pad
#define SA3_HI 0
#define SA3_LO (128*A_STR2)            // 18432
#define SB3_HI (2*128*A_STR2)          // 36864
#define SB3_LO (SB3_HI + 64*B_STR3)    // 70656
#define STG3   (SB3_LO + 64*B_STR3)    // 104448
#define GEMM4_SMEM (2*STG3)            // 208896

// ---------------- attention smem (3-stage) ----------------
#define AT_KH 0
#define AT_KL 8192
#define AT_VH 16384
#define AT_VL 24576
#define AT_STG 32768
#define ATTN3_SMEM (3*AT_STG)          // 98304

// ---------------- device scratch ----------------
__device__ float g_aug[2*STREAM];            // fp32 residual
__device__ float g_proj[2*STREAM];           // out-proj fp32 result
__device__ __nv_bfloat16 g_augH[2*STREAM], g_augL[2*STREAM];
__device__ __nv_bfloat16 g_QH[2*STREAM], g_QL[2*STREAM];
__device__ __nv_bfloat16 g_KH[2*STREAM], g_KL[2*STREAM];
__device__ __nv_bfloat16 g_VH[2*STREAM], g_VL[2*STREAM];
__device__ __nv_bfloat16 g_attH[2*STREAM], g_attL[2*STREAM];
__device__ __nv_bfloat16 g_WH[4*WSZ], g_WL[4*WSZ];

// ---------------- helpers ----------------
__device__ __forceinline__ uint32_t smem_u32(const void* p) {
    uint32_t a;
    asm("{ .reg .u64 t; cvta.to.shared.u64 t, %1; cvt.u32.u64 %0, t; }" : "=r"(a) : "l"(p));
    return a;
}
__device__ __forceinline__ void mma16816(float* d, const uint32_t* a, const uint32_t* b) {
    asm volatile(
        "mma.sync.aligned.m16n8k16.row.col.f32.bf16.bf16.f32 "
        "{%0,%1,%2,%3}, {%4,%5,%6,%7}, {%8,%9}, {%0,%1,%2,%3};"
        : "+f"(d[0]), "+f"(d[1]), "+f"(d[2]), "+f"(d[3])
        : "r"(a[0]), "r"(a[1]), "r"(a[2]), "r"(a[3]), "r"(b[0]), "r"(b[1]));
}
__device__ __forceinline__ void ldmx4(uint32_t* r, uint32_t addr) {
    asm volatile("ldmatrix.sync.aligned.m8n8.x4.shared.b16 {%0,%1,%2,%3}, [%4];"
                 : "=r"(r[0]), "=r"(r[1]), "=r"(r[2]), "=r"(r[3]) : "r"(addr));
}
__device__ __forceinline__ void ldmx4t(uint32_t* r, uint32_t addr) {
    asm volatile("ldmatrix.sync.aligned.m8n8.x4.trans.shared.b16 {%0,%1,%2,%3}, [%4];"
                 : "=r"(r[0]), "=r"(r[1]), "=r"(r[2]), "=r"(r[3]) : "r"(addr));
}
__device__ __forceinline__ void cpasync16(uint32_t dst, const void* src, int sz) {
    asm volatile("cp.async.cg.shared.global [%0], [%1], 16, %2;"
                 :: "r"(dst), "l"(src), "r"(sz));
}
__device__ __forceinline__ void cpcommit() { asm volatile("cp.async.commit_group;" ::: "memory"); }
template<int N> __device__ __forceinline__ void cpwait() {
    asm volatile("cp.async.wait_group %0;" :: "n"(N) : "memory");
}
__device__ __forceinline__ uint32_t pk_bf2(__nv_bfloat16 a, __nv_bfloat16 b) {
    __nv_bfloat162 t(a, b);
    return *reinterpret_cast<uint32_t*>(&t);
}
__device__ __forceinline__ void split2(float f, __nv_bfloat16& h, __nv_bfloat16& l) {
    h = __float2bfloat16(f);
    l = __float2bfloat16(f - __bfloat162float(h));
}
__device__ __forceinline__ void split8(float4 v0, float4 v1, uint4& hi, uint4& lo) {
    __nv_bfloat16 h[8], l[8];
    float f[8] = {v0.x, v0.y, v0.z, v0.w, v1.x, v1.y, v1.z, v1.w};
#pragma unroll
    for (int j = 0; j < 8; j++) split2(f[j], h[j], l[j]);
    hi = make_uint4(pk_bf2(h[0], h[1]), pk_bf2(h[2], h[3]), pk_bf2(h[4], h[5]), pk_bf2(h[6], h[7]));
    lo = make_uint4(pk_bf2(l[0], l[1]), pk_bf2(l[2], l[3]), pk_bf2(l[4], l[5]), pk_bf2(l[6], l[7]));
}

// ---------------- build augmented sequences (fp32 + split bf16) ----------------
__global__ void build_aug_kernel(const float* __restrict__ cnn,
                                 const float* __restrict__ llm,
                                 const float* __restrict__ energy,
                                 const float* __restrict__ mass,
                                 const float* __restrict__ momentum) {
    int idx = blockIdx.x * blockDim.x + threadIdx.x;   // 8-float unit
    const int total = BB * SA * HID / 8;
    if (idx >= total) return;
    int h8  = idx % (HID / 8);
    int row = idx / (HID / 8);
    int s   = row % SA;
    int b   = row / SA;
    float4 c0, c1, l0, l1;
    if (s < SS) {
        const float* cp = cnn + ((size_t)(b * SS + s) * HID) + h8 * 8;
        const float* lp = llm + ((size_t)(b * SS + s) * HID) + h8 * 8;
        c0 = *(const float4*)cp; c1 = *(const float4*)(cp + 4);
        l0 = *(const float4*)lp; l1 = *(const float4*)(lp + 4);
    } else {
        const float* e = (s == SS) ? energy : ((s == SS + 1) ? mass : momentum);
        c0 = *(const float4*)(e + h8 * 8); c1 = *(const float4*)(e + h8 * 8 + 4);
        l0 = c0; l1 = c1;
    }
    size_t o = (size_t)idx * 8;
    *(float4*)&g_aug[o] = c0; *(float4*)&g_aug[o + 4] = c1;
    *(float4*)&g_aug[STREAM + o] = l0; *(float4*)&g_aug[STREAM + o + 4] = l1;
    uint4 hi, lo;
    split8(c0, c1, hi, lo);
    *(uint4*)&g_augH[o] = hi; *(uint4*)&g_augL[o] = lo;
    split8(l0, l1, hi, lo);
    *(uint4*)&g_augH[STREAM + o] = hi; *(uint4*)&g_augL[STREAM + o] = lo;
}

// ---------------- split weights once ----------------
__global__ void split_w_kernel(const float* __restrict__ W0, const float* __restrict__ W1,
                               const float* __restrict__ W2, const float* __restrict__ W3) {
    int idx = blockIdx.x * blockDim.x + threadIdx.x;   // 8-elem unit
    if (idx >= WSZ / 8) return;
    int w = blockIdx.y;
    const float* src = (w == 0) ? W0 : (w == 1) ? W1 : (w == 2) ? W2 : W3;
    const float* p = src + (size_t)idx * 8;
    float4 v0 = *(const float4*)p, v1 = *(const float4*)(p + 4);
    uint4 hi, lo;
    split8(v0, v1, hi, lo);
    size_t o = (size_t)w * WSZ + (size_t)idx * 8;
    *(uint4*)&g_WH[o] = hi;
    *(uint4*)&g_WL[o] = lo;
}

// ---------------- GEMM v4 core: warp 64x64, 6:1 MMA:LDSM ----------------
__device__ __forceinline__ void gemm4_load_stage(
    uint32_t sb, int stg, int ch, int tid,
    const __nv_bfloat16* AH, const __nv_bfloat16* AL,
    const __nv_bfloat16* WH, const __nv_bfloat16* WL,
    int row0, int col0, int M) {
    uint32_t base = sb + stg * STG3;
    // A tile: 128 rows x 8 16B-chunks (hi+lo)
#pragma unroll
    for (int i = 0; i < 4; i++) {
        int c = tid + i * 256;
        int row = c >> 3, col = c & 7;
        int gr = row0 + row;
        int sz = (gr < M) ? 16 : 0;
        size_t so = (size_t)(sz ? gr : 0) * HID + ch * KC2 + col * 8;
        uint32_t d = base + row * A_STR2 + col * 16;
        cpasync16(d + SA3_HI, AH + so, sz);
        cpasync16(d + SA3_LO, AL + so, sz);
    }
    // B tile: 64 k-rows x 32 16B-chunks (256 cols) (hi+lo)
#pragma unroll
    for (int i = 0; i < 8; i++) {
        int c = tid + i * 256;
        int row = c >> 5, col = c & 31;
        size_t so = (size_t)(ch * KC2 + row) * HID + col0 + col * 8;
        uint32_t d = base + row * B_STR3 + col * 16;
        cpasync16(d + SB3_HI, WH + so, 16);
        cpasync16(d + SB3_LO, WL + so, 16);
    }
}

__device__ __forceinline__ void gemm4_core(
    const __nv_bfloat16* __restrict__ AH, const __nv_bfloat16* __restrict__ AL,
    const __nv_bfloat16* __restrict__ WH, const __nv_bfloat16* __restrict__ WL,
    const float* __restrict__ bias, float* __restrict__ Cf,
    __nv_bfloat16* __restrict__ CH, __nv_bfloat16* __restrict__ CL, int M) {
    extern __shared__ char smc[];
    const uint32_t sb = smem_u32(smc);
    const int tid = threadIdx.x, lane = tid & 31, wid = tid >> 5;
    const int wm = wid >> 2, wn = wid & 3;   // 2m x 4n warps, 64x64 tiles
    const int row0 = blockIdx.y * TM, col0 = blockIdx.x * TN3;

    float acc[4][8][4];
#pragma unroll
    for (int i = 0; i < 4; i++)
#pragma unroll
        for (int j = 0; j < 8; j++)
#pragma unroll
            for (int k = 0; k < 4; k++) acc[i][j][k] = 0.f;

    const uint32_t a_lane = (uint32_t)((lane & 15) * A_STR2 + (lane >> 4) * 16);
    const uint32_t b_lane = (uint32_t)(((((lane >> 3) & 1) * 8) + (lane & 7)) * B_STR3
                                       + (lane >> 4) * 16);

    gemm4_load_stage(sb, 0, 0, tid, AH, AL, WH, WL, row0, col0, M);
    cpcommit();

    for (int ch = 0; ch < NCH2; ch++) {
        if (ch + 1 < NCH2) {
            gemm4_load_stage(sb, (ch + 1) & 1, ch + 1, tid, AH, AL, WH, WL, row0, col0, M);
            cpcommit();
            cpwait<1>();
        } else {
            cpwait<0>();
        }
        __syncthreads();

        const uint32_t stg = sb + (ch & 1) * STG3;
#pragma unroll
        for (int ks = 0; ks < 4; ks++) {
            uint32_t bhi[8][2], blo[8][2];
            const uint32_t bo = stg + (uint32_t)(ks * 16 * B_STR3 + wn * 128) + b_lane;
#pragma unroll
            for (int g = 0; g < 4; g++) {
                uint32_t t[4];
                ldmx4t(t, bo + SB3_HI + g * 32);
                bhi[2*g][0] = t[0]; bhi[2*g][1] = t[1];
                bhi[2*g+1][0] = t[2]; bhi[2*g+1][1] = t[3];
                ldmx4t(t, bo + SB3_LO + g * 32);
                blo[2*g][0] = t[0]; blo[2*g][1] = t[1];
                blo[2*g+1][0] = t[2]; blo[2*g+1][1] = t[3];
            }
#pragma unroll
            for (int mt = 0; mt < 4; mt++) {
                uint32_t ah[4], al[4];
                uint32_t ao = stg + (uint32_t)((wm * 64 + mt * 16) * A_STR2 + ks * 32) + a_lane;
                ldmx4(ah, ao + SA3_HI);
                ldmx4(al, ao + SA3_LO);
#pragma unroll
                for (int nt = 0; nt < 8; nt++) {
                    mma16816(acc[mt][nt], ah, bhi[nt]);
                    mma16816(acc[mt][nt], ah, blo[nt]);
                    mma16816(acc[mt][nt], al, bhi[nt]);
                }
            }
        }
        __syncthreads();
    }

    const int mb = row0 + wm * 64 + (lane >> 2);
    const int nb = col0 + wn * 64 + (lane & 3) * 2;
    if (CH) {
#pragma unroll
        for (int nt = 0; nt < 8; nt++) {
            const int n = nb + nt * 8;
            const float2 bv = *(const float2*)&bias[n];
#pragma unroll
            for (int mt = 0; mt < 4; mt++) {
                const int m = mb + mt * 16;
                if (m < M) {
                    float x = acc[mt][nt][0] + bv.x, y = acc[mt][nt][1] + bv.y;
                    __nv_bfloat16 hx, lx, hy, ly;
                    split2(x, hx, lx); split2(y, hy, ly);
                    *(uint32_t*)&CH[(size_t)m * HID + n] = pk_bf2(hx, hy);
                    *(uint32_t*)&CL[(size_t)m * HID + n] = pk_bf2(lx, ly);
                }
                if (m + 8 < M) {
                    float x = acc[mt][nt][2] + bv.x, y = acc[mt][nt][3] + bv.y;
                    __nv_bfloat16 hx, lx, hy, ly;
                    split2(x, hx, lx); split2(y, hy, ly);
                    *(uint32_t*)&CH[(size_t)(m + 8) * HID + n] = pk_bf2(hx, hy);
                    *(uint32_t*)&CL[(size_t)(m + 8) * HID + n] = pk_bf2(lx, ly);
                }
            }
        }
    } else {
#pragma unroll
        for (int nt = 0; nt < 8; nt++) {
            const int n = nb + nt * 8;
            const float2 bv = *(const float2*)&bias[n];
#pragma unroll
            for (int mt = 0; mt < 4; mt++) {
                const int m = mb + mt * 16;
                if (m < M)
                    *(float2*)&Cf[(size_t)m * HID + n] =
                        make_float2(acc[mt][nt][0] + bv.x, acc[mt][nt][1] + bv.y);
                if (m + 8 < M)
                    *(float2*)&Cf[(size_t)(m + 8) * HID + n] =
                        make_float2(acc[mt][nt][2] + bv.x, acc[mt][nt][3] + bv.y);
            }
        }
    }
}

// merged Q/K/V projection: blockIdx.z selects weight/bias/output
__global__ __launch_bounds__(256, 1) void gemm4_qkv_kernel(
    const float* __restrict__ bq, const float* __restrict__ bk, const float* __restrict__ bv) {
    const int z = blockIdx.z;
    const float* bias = (z == 0) ? bq : (z == 1) ? bk : bv;
    __nv_bfloat16* CH = (z == 0) ? g_QH : (z == 1) ? g_KH : g_VH;
    __nv_bfloat16* CL = (z == 0) ? g_QL : (z == 1) ? g_KL : g_VL;
    gemm4_core(g_augH, g_augL, g_WH + (size_t)z * WSZ, g_WL + (size_t)z * WSZ,
               bias, nullptr, CH, CL, MTOT2);
}

// output projection (fp32 out)
__global__ __launch_bounds__(256, 1) void gemm4_o_kernel(const float* __restrict__ bo) {
    gemm4_core(g_attH, g_attL, g_WH + 3 * (size_t)WSZ, g_WL + 3 * (size_t)WSZ,
               bo, g_proj, nullptr, nullptr, MTOT2);
}

// ---------------- attention: 512 threads, Br=256, 3-stage cp.async ----------------
__device__ __forceinline__ void attn3_load_arr(
    uint32_t dstbase, const __nv_bfloat16* src, size_t baseBH, int k0, int tid) {
    int row = tid >> 3, col = tid & 7;
    int gr = k0 + row;
    int sz = (gr < SA) ? 16 : 0;
    const __nv_bfloat16* s = src + baseBH + (size_t)(sz ? gr : 0) * HID + col * 8;
    cpasync16(dstbase + SWZ((uint32_t)(row * 128 + col * 16)), s, sz);
}

__global__ __launch_bounds__(512, 1) void attn3_kernel() {
    extern __shared__ char smc[];
    const uint32_t sb = smem_u32(smc);
    const int tid = threadIdx.x, lane = tid & 31, wid = tid >> 5;
    const int qt = blockIdx.x, bh = blockIdx.y, z = blockIdx.z;
    const int b = bh >> 4, h = bh & 15;

    const __nv_bfloat16* QH = g_QH + (size_t)z * STREAM;
    const __nv_bfloat16* QL = g_QL + (size_t)z * STREAM;
    const __nv_bfloat16* KH = g_KH + (size_t)(1 - z) * STREAM;
    const __nv_bfloat16* KL = g_KL + (size_t)(1 - z) * STREAM;
    const __nv_bfloat16* VH = g_VH + (size_t)(1 - z) * STREAM;
    const __nv_bfloat16* VL = g_VL + (size_t)(1 - z) * STREAM;
    __nv_bfloat16* OH = g_attH + (size_t)z * STREAM;
    __nv_bfloat16* OL = g_attL + (size_t)z * STREAM;
    const size_t baseBH = (size_t)b * SA * HID + h * HD;
    const int q0 = qt * 256;

    // ---- stage Q in two 128-row halves; each half of the warps grabs its frags ----
    uint32_t qh[4][4], ql[4][4];
#pragma unroll 1
    for (int h2 = 0; h2 < 2; h2++) {
        for (int idx = tid; idx < 128 * 8; idx += 512) {
            int r = idx >> 3, c8 = (idx & 7) * 8;
            uint4 hi = make_uint4(0, 0, 0, 0), lo = hi;
            int gr = q0 + h2 * 128 + r;
            if (gr < SA) {
                size_t g = baseBH + (size_t)gr * HID + c8;
                hi = *(const uint4*)&QH[g];
                lo = *(const uint4*)&QL[g];
            }
            uint32_t off = SWZ((uint32_t)(r * 128 + c8 * 2));
            *(uint4*)(smc + off) = hi;
            *(uint4*)(smc + 16384 + off) = lo;
        }
        __syncthreads();
        if ((wid >> 3) == h2) {
#pragma unroll
            for (int ks = 0; ks < 4; ks++) {
                uint32_t off = SWZ((uint32_t)(((wid & 7) * 16 + (lane & 15)) * 128
                                              + ks * 32 + (lane >> 4) * 16));
                ldmx4(qh[ks], sb + off);
                ldmx4(ql[ks], sb + 16384 + off);
            }
        }
        __syncthreads();
    }

    float o[8][4];
#pragma unroll
    for (int n = 0; n < 8; n++)
#pragma unroll
        for (int c = 0; c < 4; c++) o[n][c] = 0.f;
    float m0r = -INFINITY, m1r = -INFINITY, l0r = 0.f, l1r = 0.f;

    const int NT = (SA + 63) / 64;   // 33

    // prologue: stages 0, 1
#pragma unroll
    for (int p = 0; p < 2; p++) {
        uint32_t pb = sb + p * AT_STG;
        attn3_load_arr(pb + AT_KH, KH, baseBH, p * 64, tid);
        attn3_load_arr(pb + AT_KL, KL, baseBH, p * 64, tid);
        attn3_load_arr(pb + AT_VH, VH, baseBH, p * 64, tid);
        attn3_load_arr(pb + AT_VL, VL, baseBH, p * 64, tid);
        cpcommit();
    }

    int slot = 0;
    for (int kt = 0; kt < NT; kt++) {
        const int k0 = kt * 64;
        if (kt + 2 < NT) {
            int ns = slot + 2; if (ns >= 3) ns -= 3;
            uint32_t nb = sb + ns * AT_STG;
            attn3_load_arr(nb + AT_KH, KH, baseBH, k0 + 128, tid);
            attn3_load_arr(nb + AT_KL, KL, baseBH, k0 + 128, tid);
            attn3_load_arr(nb + AT_VH, VH, baseBH, k0 + 128, tid);
            attn3_load_arr(nb + AT_VL, VL, baseBH, k0 + 128, tid);
            cpcommit();
            cpwait<2>();
        } else if (kt + 1 < NT) {
            cpwait<1>();
        } else {
            cpwait<0>();
        }
        __syncthreads();

        const uint32_t stg = sb + slot * AT_STG;

        // ---- S = Q @ K^T (3 split terms) ----
        float s[8][4];
#pragma unroll
        for (int n = 0; n < 8; n++)
#pragma unroll
            for (int c = 0; c < 4; c++) s[n][c] = 0.f;

#pragma unroll
        for (int kt2 = 0; kt2 < 4; kt2++) {
#pragma unroll
            for (int ks = 0; ks < 4; ks++) {
                uint32_t off = SWZ((uint32_t)((kt2 * 16 + (lane & 15)) * 128 + ks * 32 + (lane >> 4) * 16));
                uint32_t kb[4], kl[4];
                ldmx4(kb, stg + AT_KH + off);
                ldmx4(kl, stg + AT_KL + off);
                uint32_t blo_h[2] = {kb[0], kb[2]}, bhi_h[2] = {kb[1], kb[3]};
                uint32_t blo_l[2] = {kl[0], kl[2]}, bhi_l[2] = {kl[1], kl[3]};
                mma16816(s[2*kt2],     qh[ks], blo_h);
                mma16816(s[2*kt2],     qh[ks], blo_l);
                mma16816(s[2*kt2],     ql[ks], blo_h);
                mma16816(s[2*kt2 + 1], qh[ks], bhi_h);
                mma16816(s[2*kt2 + 1], qh[ks], bhi_l);
                mma16816(s[2*kt2 + 1], ql[ks], bhi_h);
            }
        }

        // ---- scale + mask ----
#pragma unroll
        for (int n = 0; n < 8; n++)
#pragma unroll
            for (int c = 0; c < 4; c++) s[n][c] *= 0.125f;
        if (k0 + 64 > SA) {
#pragma unroll
            for (int n = 0; n < 8; n++) {
                int ktc = k0 + (n >> 1) * 16 + (n & 1) * 8 + (lane & 3) * 2;
#pragma unroll
                for (int c = 0; c < 4; c++)
                    if (ktc + (c & 1) >= SA) s[n][c] = -1e30f;
            }
        }

        // ---- online softmax ----
        float mx0 = -INFINITY, mx1 = -INFINITY;
#pragma unroll
        for (int n = 0; n < 8; n++) {
            mx0 = fmaxf(mx0, fmaxf(s[n][0], s[n][1]));
            mx1 = fmaxf(mx1, fmaxf(s[n][2], s[n][3]));
        }
#pragma unroll
        for (int msk = 1; msk <= 2; msk <<= 1) {
            mx0 = fmaxf(mx0, __shfl_xor_sync(0xffffffffu, mx0, msk));
            mx1 = fmaxf(mx1, __shfl_xor_sync(0xffffffffu, mx1, msk));
        }
        float mn0 = fmaxf(m0r, mx0), mn1 = fmaxf(m1r, mx1);
        float c0 = __expf(m0r - mn0), c1 = __expf(m1r - mn1);
        m0r = mn0; m1r = mn1;
        float rs0 = 0.f, rs1 = 0.f;
#pragma unroll
        for (int n = 0; n < 8; n++) {
            s[n][0] = __expf(s[n][0] - mn0); rs0 += s[n][0];
            s[n][1] = __expf(s[n][1] - mn0); rs0 += s[n][1];
            s[n][2] = __expf(s[n][2] - mn1); rs1 += s[n][2];
            s[n][3] = __expf(s[n][3] - mn1); rs1 += s[n][3];
        }
#pragma unroll
        for (int msk = 1; msk <= 2; msk <<= 1) {
            rs0 += __shfl_xor_sync(0xffffffffu, rs0, msk);
            rs1 += __shfl_xor_sync(0xffffffffu, rs1, msk);
        }
        l0r = l0r * c0 + rs0;
        l1r = l1r * c1 + rs1;
#pragma unroll
        for (int n = 0; n < 8; n++) {
            o[n][0] *= c0; o[n][1] *= c0; o[n][2] *= c1; o[n][3] *= c1;
        }

        // ---- pack P (split) into a-frags ----
        uint32_t pah[4][4], pal[4][4];
#pragma unroll
        for (int ks = 0; ks < 4; ks++) {
            const int j0 = 2 * ks, j1 = 2 * ks + 1;
            __nv_bfloat16 hh[8], ll[8];
            split2(s[j0][0], hh[0], ll[0]); split2(s[j0][1], hh[1], ll[1]);
            split2(s[j0][2], hh[2], ll[2]); split2(s[j0][3], hh[3], ll[3]);
            split2(s[j1][0], hh[4], ll[4]); split2(s[j1][1], hh[5], ll[5]);
            split2(s[j1][2], hh[6], ll[6]); split2(s[j1][3], hh[7], ll[7]);
            pah[ks][0] = pk_bf2(hh[0], hh[1]); pah[ks][1] = pk_bf2(hh[2], hh[3]);
            pah[ks][2] = pk_bf2(hh[4], hh[5]); pah[ks][3] = pk_bf2(hh[6], hh[7]);
            pal[ks][0] = pk_bf2(ll[0], ll[1]); pal[ks][1] = pk_bf2(ll[2], ll[3]);
            pal[ks][2] = pk_bf2(ll[4], ll[5]); pal[ks][3] = pk_bf2(ll[6], ll[7]);
        }

        // ---- O += P @ V ----
        const uint32_t rp = ((lane >> 3) & 1) * 8 + (lane & 7);
#pragma unroll
        for (int dt = 0; dt < 4; dt++) {
#pragma unroll
            for (int ks = 0; ks < 4; ks++) {
                uint32_t off = SWZ((uint32_t)((ks * 16 + rp) * 128 + dt * 32 + (lane >> 4) * 16));
                uint32_t vb[4], vl[4];
                ldmx4t(vb, stg + AT_VH + off);
                ldmx4t(vl, stg + AT_VL + off);
                uint32_t b0h[2] = {vb[0], vb[1]}, b1h[2] = {vb[2], vb[3]};
                uint32_t b0l[2] = {vl[0], vl[1]}, b1l[2] = {vl[2], vl[3]};
                mma16816(o[2*dt],     pah[ks], b0h);
                mma16816(o[2*dt],     pah[ks], b0l);
                mma16816(o[2*dt],     pal[ks], b0h);
                mma16816(o[2*dt + 1], pah[ks], b1h);
                mma16816(o[2*dt + 1], pah[ks], b1l);
                mma16816(o[2*dt + 1], pal[ks], b1h);
            }
        }
        __syncthreads();
        if (++slot == 3) slot = 0;
    }

    // ---- epilogue: normalize, split, store ----
    const int r0 = q0 + wid * 16 + (lane >> 2);
    const float inv0 = 1.0f / l0r, inv1 = 1.0f / l1r;
#pragma unroll
    for (int n = 0; n < 8; n++) {
        const int col = (n >> 1) * 16 + (n & 1) * 8 + (lane & 3) * 2;
        if (r0 < SA) {
            float x = o[n][0] * inv0, y = o[n][1] * inv0;
            __nv_bfloat16 hx, lx, hy, ly;
            split2(x, hx, lx); split2(y, hy, ly);
            size_t g = baseBH + (size_t)r0 * HID + col;
            *(uint32_t*)&OH[g] = pk_bf2(hx, hy);
            *(uint32_t*)&OL[g] = pk_bf2(lx, ly);
        }
        if (r0 + 8 < SA) {
            float x = o[n][2] * inv1, y = o[n][3] * inv1;
            __nv_bfloat16 hx, lx, hy, ly;
            split2(x, hx, lx); split2(y, hy, ly);
            size_t g = baseBH + (size_t)(r0 + 8) * HID + col;
            *(uint32_t*)&OH[g] = pk_bf2(hx, hy);
            *(uint32_t*)&OL[g] = pk_bf2(lx, ly);
        }
    }
}

// ---------------- residual + LayerNorm + slice -> output ----------------
__global__ __launch_bounds__(128) void ln_out_kernel(
    const float* __restrict__ gamma, const float* __restrict__ beta,
    float* __restrict__ out) {
    __shared__ float sbuf[4];
    const int row = blockIdx.x;
    const int c = row >> 12;
    const int r = row & 4095;
    const int b = r >> 11;
    const int s = r & 2047;
    const float* aug  = g_aug  + (size_t)c * STREAM;
    const float* proj = g_proj + (size_t)c * STREAM;
    const size_t base = ((size_t)b * SA + s) * HID;
    const int tid = threadIdx.x;

    float x[8];
    float4 a0 = *(const float4*)&aug[base + tid * 8];
    float4 a1 = *(const float4*)&aug[base + tid * 8 + 4];
    float4 p0 = *(const float4*)&proj[base + tid * 8];
    float4 p1 = *(const float4*)&proj[base + tid * 8 + 4];
    x[0] = a0.x + p0.x; x[1] = a0.y + p0.y; x[2] = a0.z + p0.z; x[3] = a0.w + p0.w;
    x[4] = a1.x + p1.x; x[5] = a1.y + p1.y; x[6] = a1.z + p1.z; x[7] = a1.w + p1.w;

    float sum = 0.f;
#pragma unroll
    for (int j = 0; j < 8; j++) sum += x[j];
#pragma unroll
    for (int m = 16; m >= 1; m >>= 1) sum += __shfl_xor_sync(0xffffffffu, sum, m);
    if ((tid & 31) == 0) sbuf[tid >> 5] = sum;
    __syncthreads();
    float mu = (sbuf[0] + sbuf[1] + sbuf[2] + sbuf[3]) * (1.0f / HID);
    __syncthreads();

    float vs = 0.f;
#pragma unroll
    for (int j = 0; j < 8; j++) { float d = x[j] - mu; vs += d * d; }
#pragma unroll
    for (int m = 16; m >= 1; m >>= 1) vs += __shfl_xor_sync(0xffffffffu, vs, m);
    if ((tid & 31) == 0) sbuf[tid >> 5] = vs;
    __syncthreads();
    float var = (sbuf[0] + sbuf[1] + sbuf[2] + sbuf[3]) * (1.0f / HID);
    float rstd = rsqrtf(var + 1e-5f);

    float* op = out + (size_t)c * (BB * SS * HID) + ((size_t)b * SS + s) * HID + tid * 8;
    float o[8];
#pragma unroll
    for (int j = 0; j < 8; j++) {
        int col = tid * 8 + j;
        o[j] = (x[j] - mu) * rstd * gamma[col] + beta[col];
    }
    *(float4*)(op)     = make_float4(o[0], o[1], o[2], o[3]);
    *(float4*)(op + 4) = make_float4(o[4], o[5], o[6], o[7]);
}

// ---------------- launch ----------------
extern "C" void kernel_launch(void* const* d_in, const int* in_sizes, int n_in,
                              void* d_out, int out_size) {
    const float* cnn      = (const float*)d_in[0];
    const float* llm      = (const float*)d_in[1];
    const float* Wq       = (const float*)d_in[2];
    const float* bq       = (const float*)d_in[3];
    const float* Wk       = (const float*)d_in[4];
    const float* bk       = (const float*)d_in[5];
    const float* Wv       = (const float*)d_in[6];
    const float* bv       = (const float*)d_in[7];
    const float* Wo       = (const float*)d_in[8];
    const float* bo       = (const float*)d_in[9];
    const float* energy   = (const float*)d_in[10];
    const float* mass     = (const float*)d_in[11];
    const float* momentum = (const float*)d_in[12];
    const float* gamma    = (const float*)d_in[13];
    const float* beta     = (const float*)d_in[14];
    float* out = (float*)d_out;

    const int tot8 = BB * SA * HID / 8;
    build_aug_kernel<<<(tot8 + 255) / 256, 256>>>(cnn, llm, energy, mass, momentum);

    dim3 wgrid(WSZ / 8 / 256, 4);
    split_w_kernel<<<wgrid, 256>>>(Wq, Wk, Wv, Wo);

    cudaFuncSetAttribute(gemm4_qkv_kernel, cudaFuncAttributeMaxDynamicSharedMemorySize, GEMM4_SMEM);
    cudaFuncSetAttribute(gemm4_o_kernel, cudaFuncAttributeMaxDynamicSharedMemorySize, GEMM4_SMEM);
    dim3 ggrid(HID / TN3, (MTOT2 + TM - 1) / TM, 3);   // (4, 65, 3)
    gemm4_qkv_kernel<<<ggrid, 256, GEMM4_SMEM>>>(bq, bk, bv);

    cudaFuncSetAttribute(attn3_kernel, cudaFuncAttributeMaxDynamicSharedMemorySize, ATTN3_SMEM);
    dim3 agrid((SA + 255) / 256, BB * NH, 2);          // (9, 32, 2)
    attn3_kernel<<<agrid, 512, ATTN3_SMEM>>>();

    dim3 ogrid(HID / TN3, (MTOT2 + TM - 1) / TM, 1);   // (4, 65)
    gemm4_o_kernel<<<ogrid, 256, GEMM4_SMEM>>>(bo);

    ln_out_kernel<<<2 * BB * SS, 128>>>(gamma, beta, out);
}